// round 10
// baseline (speedup 1.0000x reference)
#include <cuda_runtime.h>
#include <cuda_fp16.h>
#include <math.h>
#include <stdint.h>

#define B_    2
#define S_    2048
#define HID_  512
#define H_    8
#define BH_   16
#define M_    4096

// Scratch (device globals; no allocation allowed)
__device__ __align__(256) __half g_Qh[M_ * HID_];
__device__ __align__(256) __half g_Kh[M_ * HID_];
__device__ __align__(256) __half g_Vh[M_ * HID_];
__device__ __align__(256) __half g_Vt[BH_ * 64 * S_];   // [z][d][s]
__device__ __align__(256) __half g_Xh[M_ * HID_];
__device__ float g_rowinv[BH_ * S_];
__device__ uint32_t g_pm[M_ * 64];                      // packed mask bits, 1MB
__device__ float g_attn_scratch[(size_t)BH_ * S_ * S_];

// ---------------------------------------------------------------------------
// helpers
// ---------------------------------------------------------------------------
__device__ __forceinline__ unsigned f2h2(float a, float b) {
    __half2 h = __floats2half2_rn(a, b);
    return *(unsigned*)&h;
}
__device__ __forceinline__ unsigned f2h2v(float2 v) { return f2h2(v.x, v.y); }

__device__ __forceinline__ void mmah(float c[4], const unsigned a[4], const unsigned b[2]) {
    asm volatile(
        "mma.sync.aligned.m16n8k16.row.col.f32.f16.f16.f32 "
        "{%0,%1,%2,%3},{%4,%5,%6,%7},{%8,%9},{%0,%1,%2,%3};"
        : "+f"(c[0]), "+f"(c[1]), "+f"(c[2]), "+f"(c[3])
        : "r"(a[0]), "r"(a[1]), "r"(a[2]), "r"(a[3]),
          "r"(b[0]), "r"(b[1]));
}

__device__ __forceinline__ void cp16(uint32_t saddr, const void* g) {
    asm volatile("cp.async.cg.shared.global [%0], [%1], 16;" :: "r"(saddr), "l"(g));
}
__device__ __forceinline__ uint32_t sptr(const void* p) {
    return (uint32_t)__cvta_generic_to_shared(p);
}

// ---------------------------------------------------------------------------
// QKV projection (fp32 in, fp16 mma, fp16 out): Y = (X @ W^T + b) * scale
// 128m x 64n tile, 32-k stages x3, 2 CTAs/SM.
// ---------------------------------------------------------------------------
struct ProjArgs { const float *X, *W, *b; __half *Yh; float scale; };

#define PJ_A(s) ((s) * 6912)
#define PJ_B(s) ((s) * 6912 + 4608)
#define PJ_SMEM (3 * 6912 * 4)

__global__ void __launch_bounds__(256, 2)
proj_qkv(ProjArgs a0, ProjArgs a1, ProjArgs a2)
{
    const ProjArgs& A_ = (blockIdx.z == 0) ? a0 : (blockIdx.z == 1) ? a1 : a2;
    const float* __restrict__ Xg = A_.X;
    const float* __restrict__ Wg = A_.W;
    const float* __restrict__ bias = A_.b;

    extern __shared__ float psm[];
    const uint32_t sb = sptr(psm);

    const int tid = threadIdx.x;
    const int lane = tid & 31, wid = tid >> 5;
    const int g = lane >> 2, tg = lane & 3;
    const int wm = wid & 3, wn = wid >> 2;
    const int m0 = blockIdx.y * 128, n0 = blockIdx.x * 64;

    auto stage = [&](int k0, int s) {
        #pragma unroll
        for (int j = 0; j < 4; j++) {
            int lin = tid + j * 256;
            int r = lin >> 3, c4 = lin & 7;
            cp16(sb + (PJ_A(s) + r * 36 + c4 * 4) * 4,
                 Xg + (size_t)(m0 + r) * 512 + k0 + c4 * 4);
        }
        #pragma unroll
        for (int j = 0; j < 2; j++) {
            int lin = tid + j * 256;
            int r = lin >> 3, c4 = lin & 7;
            cp16(sb + (PJ_B(s) + r * 36 + c4 * 4) * 4,
                 Wg + (size_t)(n0 + r) * 512 + k0 + c4 * 4);
        }
        asm volatile("cp.async.commit_group;");
    };

    float acc[2][4][4] = {};

    stage(0, 0);
    stage(32, 1);
    for (int t = 0; t < 16; t++) {
        if (t < 15) asm volatile("cp.async.wait_group 1;");
        else        asm volatile("cp.async.wait_group 0;");
        __syncthreads();
        if (t + 2 < 16) stage((t + 2) * 32, (t + 2) % 3);

        const float* As = psm + PJ_A(t % 3);
        const float* Bs = psm + PJ_B(t % 3);

        #pragma unroll
        for (int ks = 0; ks < 2; ks++) {
            unsigned af[2][4], bf[4][2];
            #pragma unroll
            for (int mi = 0; mi < 2; mi++) {
                const float* b0 = &As[(wm * 32 + mi * 16 + g) * 36 + ks * 16 + 2 * tg];
                const float* b1 = b0 + 8 * 36;
                af[mi][0] = f2h2v(*(const float2*)b0);
                af[mi][1] = f2h2v(*(const float2*)b1);
                af[mi][2] = f2h2v(*(const float2*)(b0 + 8));
                af[mi][3] = f2h2v(*(const float2*)(b1 + 8));
            }
            #pragma unroll
            for (int ni = 0; ni < 4; ni++) {
                const float* bb = &Bs[(wn * 32 + ni * 8 + g) * 36 + ks * 16 + 2 * tg];
                bf[ni][0] = f2h2v(*(const float2*)bb);
                bf[ni][1] = f2h2v(*(const float2*)(bb + 8));
            }
            #pragma unroll
            for (int mi = 0; mi < 2; mi++)
                #pragma unroll
                for (int ni = 0; ni < 4; ni++)
                    mmah(acc[mi][ni], af[mi], bf[ni]);
        }
    }

    const float scale = A_.scale;
    #pragma unroll
    for (int mi = 0; mi < 2; mi++) {
        int r0 = m0 + wm * 32 + mi * 16 + g;
        #pragma unroll
        for (int ni = 0; ni < 4; ni++) {
            int c0 = n0 + wn * 32 + ni * 8 + 2 * tg;
            float b0v = __ldg(bias + c0), b1v = __ldg(bias + c0 + 1);
            __half2 h0 = __floats2half2_rn((acc[mi][ni][0] + b0v) * scale,
                                           (acc[mi][ni][1] + b1v) * scale);
            __half2 h1 = __floats2half2_rn((acc[mi][ni][2] + b0v) * scale,
                                           (acc[mi][ni][3] + b1v) * scale);
            *(__half2*)(A_.Yh + (size_t)r0 * 512 + c0) = h0;
            *(__half2*)(A_.Yh + (size_t)(r0 + 8) * 512 + c0) = h1;
        }
    }
}

// ---------------------------------------------------------------------------
// Output projection (fp16 X in, fp32 W, fp32 out), 3 CTAs/SM.
// X smem row stride = 40 halves (80 bytes, 16B-aligned for cp.async).
// ---------------------------------------------------------------------------
#define PO_STAGE 19456
#define PO_X(s) ((s) * PO_STAGE)
#define PO_W(s) ((s) * PO_STAGE + 10240)
#define PO_SMEM (3 * PO_STAGE)

__global__ void __launch_bounds__(256, 3)
proj_out(const __half* __restrict__ Xg, const float* __restrict__ Wg,
         const float* __restrict__ bias, float* __restrict__ Y)
{
    extern __shared__ char posm[];
    const uint32_t sb = sptr(posm);

    const int tid = threadIdx.x;
    const int lane = tid & 31, wid = tid >> 5;
    const int g = lane >> 2, tg = lane & 3;
    const int wm = wid & 3, wn = wid >> 2;
    const int m0 = blockIdx.y * 128, n0 = blockIdx.x * 64;

    auto stage = [&](int k0, int s) {
        #pragma unroll
        for (int j = 0; j < 2; j++) {
            int lin = tid + j * 256;
            int r = lin >> 2, c16 = lin & 3;
            cp16(sb + PO_X(s) + (uint32_t)r * 80u + (uint32_t)c16 * 16u,
                 Xg + (size_t)(m0 + r) * 512 + k0 + c16 * 8);
        }
        #pragma unroll
        for (int j = 0; j < 2; j++) {
            int lin = tid + j * 256;
            int r = lin >> 3, c4 = lin & 7;
            cp16(sb + PO_W(s) + (uint32_t)r * 144u + (uint32_t)c4 * 16u,
                 Wg + (size_t)(n0 + r) * 512 + k0 + c4 * 4);
        }
        asm volatile("cp.async.commit_group;");
    };

    float acc[2][4][4] = {};

    stage(0, 0);
    stage(32, 1);
    for (int t = 0; t < 16; t++) {
        if (t < 15) asm volatile("cp.async.wait_group 1;");
        else        asm volatile("cp.async.wait_group 0;");
        __syncthreads();
        if (t + 2 < 16) stage((t + 2) * 32, (t + 2) % 3);

        const __half* Xs = (const __half*)(posm + PO_X(t % 3));
        const float*  Ws = (const float*)(posm + PO_W(t % 3));

        #pragma unroll
        for (int ks = 0; ks < 2; ks++) {
            unsigned af[2][4], bf[4][2];
            #pragma unroll
            for (int mi = 0; mi < 2; mi++) {
                const __half* x0 = &Xs[(wm * 32 + mi * 16 + g) * 40 + ks * 16 + 2 * tg];
                const __half* x1 = x0 + 8 * 40;
                af[mi][0] = *(const uint32_t*)x0;
                af[mi][1] = *(const uint32_t*)x1;
                af[mi][2] = *(const uint32_t*)(x0 + 8);
                af[mi][3] = *(const uint32_t*)(x1 + 8);
            }
            #pragma unroll
            for (int ni = 0; ni < 4; ni++) {
                const float* bb = &Ws[(wn * 32 + ni * 8 + g) * 36 + ks * 16 + 2 * tg];
                bf[ni][0] = f2h2v(*(const float2*)bb);
                bf[ni][1] = f2h2v(*(const float2*)(bb + 8));
            }
            #pragma unroll
            for (int mi = 0; mi < 2; mi++)
                #pragma unroll
                for (int ni = 0; ni < 4; ni++)
                    mmah(acc[mi][ni], af[mi], bf[ni]);
        }
    }

    #pragma unroll
    for (int mi = 0; mi < 2; mi++) {
        int r0 = m0 + wm * 32 + mi * 16 + g;
        #pragma unroll
        for (int ni = 0; ni < 4; ni++) {
            int c0 = n0 + wn * 32 + ni * 8 + 2 * tg;
            float b0v = __ldg(bias + c0), b1v = __ldg(bias + c0 + 1);
            *(float2*)(Y + (size_t)r0 * 512 + c0) =
                make_float2(acc[mi][ni][0] + b0v, acc[mi][ni][1] + b1v);
            *(float2*)(Y + (size_t)(r0 + 8) * 512 + c0) =
                make_float2(acc[mi][ni][2] + b0v, acc[mi][ni][3] + b1v);
        }
    }
}

// ---------------------------------------------------------------------------
// vtrans + mask pack: Vh [b,s,hid] -> Vt [z][d][s]; mask -> pm bits.
// ---------------------------------------------------------------------------
__global__ void __launch_bounds__(256)
vtrans_pack(const __half* __restrict__ Vh, __half* __restrict__ Vt,
            const int* __restrict__ mask, uint32_t* __restrict__ pm)
{
    __shared__ __half ts[64 * 72];
    const int tid = threadIdx.x;
    const int z = blockIdx.y, bB = z >> 3, h = z & 7;
    const int s0 = blockIdx.x * 64;

    // mask pack: this block handles 512 pm words (2 per thread)
    {
        int base = (z * 32 + blockIdx.x) * 512 + tid * 2;
        #pragma unroll
        for (int w = 0; w < 2; w++) {
            int widx = base + w;
            int row = widx >> 6, wrd = widx & 63;
            const int4* mp = (const int4*)(mask + (size_t)row * 2048 + wrd * 32);
            uint32_t u = 0;
            #pragma unroll
            for (int j = 0; j < 8; j++) {
                int4 m = __ldg(mp + j);
                u |= (m.x != 0 ? 1u : 0u) << (j * 4);
                u |= (m.y != 0 ? 1u : 0u) << (j * 4 + 1);
                u |= (m.z != 0 ? 1u : 0u) << (j * 4 + 2);
                u |= (m.w != 0 ? 1u : 0u) << (j * 4 + 3);
            }
            pm[widx] = u;
        }
    }

    #pragma unroll
    for (int j = 0; j < 8; j++) {
        int lin = tid + j * 256;
        int s = lin >> 5, du = lin & 31;
        *(uint32_t*)(ts + s * 72 + du * 2) =
            *(const uint32_t*)(Vh + (size_t)(bB * S_ + s0 + s) * HID_ + h * 64 + du * 2);
    }
    __syncthreads();
    #pragma unroll
    for (int j = 0; j < 8; j++) {
        int lin = tid + j * 256;
        int d = lin >> 5, su = lin & 31;
        __half2 o = __halves2half2(ts[(2 * su) * 72 + d], ts[(2 * su + 1) * 72 + d]);
        *(__half2*)(Vt + ((size_t)z * 64 + d) * S_ + s0 + su * 2) = o;
    }
}

// ---------------------------------------------------------------------------
// attn_A: scores+exp -> rowsum + PV (register P). pm-based mask.
// Outputs rowinv + Xh (fp16). No attn write.
// ---------------------------------------------------------------------------
#define SMB_Q    0u
#define SMB_K(s) (9216u + (s) * 18432u)
#define SMB_V(s) (64512u + (s) * 17408u)
#define SMB_RS   116736u
#define ATTN_SMEM (117008 + 16)

__global__ void __launch_bounds__(512, 1)
attn_A(const __half* __restrict__ Qh, const __half* __restrict__ Kh,
       const __half* __restrict__ Vtg, const uint32_t* __restrict__ pm,
       float* __restrict__ rowinv, __half* __restrict__ Xo)
{
    extern __shared__ char smg[];
    const uint32_t sb = sptr(smg);

    const int tid = threadIdx.x, lane = tid & 31, w = tid >> 5;
    const int g = lane >> 2, tg = lane & 3;
    const int wm = w & 3, wn = w >> 2;
    const int z = blockIdx.y, strip = blockIdx.x;
    const int bB = z >> 3, h = z & 7;
    const int s0 = strip * 64;

    float* rows = (float*)(smg + SMB_RS);
    if (tid < 64) rows[tid] = 0.f;

    const __half* Qsrc = Qh + (size_t)(bB * S_ + s0) * HID_ + h * 64;
    const __half* Ksrc = Kh + (size_t)(bB * S_) * HID_ + h * 64;
    const __half* Vsrc = Vtg + (size_t)z * 64 * S_;

    auto loadKV = [&](int chunk, int st) {
        const int kb = chunk * 128;
        #pragma unroll
        for (int j = 0; j < 2; j++) {
            int idx = tid + j * 512;
            int r = idx >> 3, c16 = idx & 7;
            cp16(sb + SMB_K(st) + (uint32_t)r * 144u + (uint32_t)c16 * 16u,
                 Ksrc + (size_t)(kb + r) * HID_ + c16 * 8);
        }
        #pragma unroll
        for (int j = 0; j < 2; j++) {
            int idx = tid + j * 512;
            int d = idx >> 4, c16 = idx & 15;
            cp16(sb + SMB_V(st) + (uint32_t)d * 272u + (uint32_t)c16 * 16u,
                 Vsrc + (size_t)d * S_ + kb + c16 * 8);
        }
        asm volatile("cp.async.commit_group;");
    };

    {
        int r = tid >> 3, c16 = tid & 7;
        cp16(sb + SMB_Q + (uint32_t)r * 144u + (uint32_t)c16 * 16u,
             Qsrc + (size_t)r * HID_ + c16 * 8);
    }
    loadKV(0, 0);
    loadKV(1, 1);
    asm volatile("cp.async.wait_group 1;");
    __syncthreads();

    const __half* Qs = (const __half*)(smg + SMB_Q);
    unsigned qa[4][4];
    #pragma unroll
    for (int ks = 0; ks < 4; ks++) {
        const __half* qr0 = Qs + (wm * 16 + g) * 72 + ks * 16 + 2 * tg;
        const __half* qr1 = qr0 + 8 * 72;
        qa[ks][0] = *(const uint32_t*)qr0;
        qa[ks][1] = *(const uint32_t*)qr1;
        qa[ks][2] = *(const uint32_t*)(qr0 + 8);
        qa[ks][3] = *(const uint32_t*)(qr1 + 8);
    }

    float pvacc[8][4] = {};
    float rsA = 0.f, rsB = 0.f;

    const int rA = bB * S_ + s0 + wm * 16 + g;   // pm row index

    for (int it = 0; it < 16; it++) {
        const int st = it % 3;

        const uint32_t wa = __ldg(pm + (uint32_t)rA * 64u + it * 4 + wn);
        const uint32_t wb = __ldg(pm + (uint32_t)(rA + 8) * 64u + it * 4 + wn);

        if (it > 0) {
            if (it < 15) asm volatile("cp.async.wait_group 1;");
            else         asm volatile("cp.async.wait_group 0;");
            __syncthreads();
        }
        if (it + 2 < 16) loadKV(it + 2, (it + 2) % 3);

        const __half* Ks = (const __half*)(smg + SMB_K(st));
        const __half* Vs = (const __half*)(smg + SMB_V(st));

        float c[4][4] = {};
        #pragma unroll
        for (int ks = 0; ks < 4; ks++) {
            #pragma unroll
            for (int nt = 0; nt < 4; nt++) {
                const __half* kp = Ks + (wn * 32 + nt * 8 + g) * 72 + ks * 16 + 2 * tg;
                unsigned b[2];
                b[0] = *(const uint32_t*)kp;
                b[1] = *(const uint32_t*)(kp + 8);
                mmah(c[nt], qa[ks], b);
            }
        }

        float p[4][4];
        #pragma unroll
        for (int nt = 0; nt < 4; nt++) {
            int sh = nt * 8 + 2 * tg;
            p[nt][0] = ((wa >> sh) & 1u)       ? __expf(c[nt][0]) : 0.f;
            p[nt][1] = ((wa >> (sh + 1)) & 1u) ? __expf(c[nt][1]) : 0.f;
            p[nt][2] = ((wb >> sh) & 1u)       ? __expf(c[nt][2]) : 0.f;
            p[nt][3] = ((wb >> (sh + 1)) & 1u) ? __expf(c[nt][3]) : 0.f;
            rsA += p[nt][0] + p[nt][1];
            rsB += p[nt][2] + p[nt][3];
        }

        unsigned pa[2][4];
        #pragma unroll
        for (int k2 = 0; k2 < 2; k2++) {
            pa[k2][0] = f2h2(p[2 * k2][0], p[2 * k2][1]);
            pa[k2][1] = f2h2(p[2 * k2][2], p[2 * k2][3]);
            pa[k2][2] = f2h2(p[2 * k2 + 1][0], p[2 * k2 + 1][1]);
            pa[k2][3] = f2h2(p[2 * k2 + 1][2], p[2 * k2 + 1][3]);
        }

        #pragma unroll
        for (int nt2 = 0; nt2 < 8; nt2++) {
            #pragma unroll
            for (int k2 = 0; k2 < 2; k2++) {
                const __half* vp = Vs + (nt2 * 8 + g) * 136 + wn * 32 + k2 * 16 + 2 * tg;
                unsigned b[2];
                b[0] = *(const uint32_t*)vp;
                b[1] = *(const uint32_t*)(vp + 8);
                mmah(pvacc[nt2], pa[k2], b);
            }
        }
    }

    rsA += __shfl_xor_sync(0xffffffffu, rsA, 1);
    rsA += __shfl_xor_sync(0xffffffffu, rsA, 2);
    rsB += __shfl_xor_sync(0xffffffffu, rsB, 1);
    rsB += __shfl_xor_sync(0xffffffffu, rsB, 2);
    if (tg == 0) {
        atomicAdd(&rows[wm * 16 + g    ], rsA);
        atomicAdd(&rows[wm * 16 + g + 8], rsB);
    }
    __syncthreads();

    if (tid < 64) {
        float inv = 1.0f / rows[tid];
        rows[tid] = inv;
        rowinv[(size_t)z * S_ + s0 + tid] = inv;
    }

    // PV cross-warp reduction: 4 disjoint areas, no atomics
    const uint32_t scrOff[4] = { SMB_V(0), SMB_V(1), SMB_V(2), SMB_K(2) };
    {
        float* sw = (float*)(smg + scrOff[wn]);
        #pragma unroll
        for (int nt2 = 0; nt2 < 8; nt2++) {
            int col = nt2 * 8 + 2 * tg;
            *(float2*)&sw[(wm * 16 + g    ) * 64 + col] =
                make_float2(pvacc[nt2][0], pvacc[nt2][1]);
            *(float2*)&sw[(wm * 16 + g + 8) * 64 + col] =
                make_float2(pvacc[nt2][2], pvacc[nt2][3]);
        }
    }
    __syncthreads();

    {
        int r = tid >> 3, cg = (tid & 7) * 8;
        float4 s0v = make_float4(0, 0, 0, 0), s1v = make_float4(0, 0, 0, 0);
        #pragma unroll
        for (int ww = 0; ww < 4; ww++) {
            const float* sw = (const float*)(smg + scrOff[ww]);
            float4 u0 = *(const float4*)&sw[r * 64 + cg];
            float4 u1 = *(const float4*)&sw[r * 64 + cg + 4];
            s0v.x += u0.x; s0v.y += u0.y; s0v.z += u0.z; s0v.w += u0.w;
            s1v.x += u1.x; s1v.y += u1.y; s1v.z += u1.z; s1v.w += u1.w;
        }
        float inv = rows[r];
        uint4 ov;
        ov.x = f2h2(s0v.x * inv, s0v.y * inv);
        ov.y = f2h2(s0v.z * inv, s0v.w * inv);
        ov.z = f2h2(s1v.x * inv, s1v.y * inv);
        ov.w = f2h2(s1v.z * inv, s1v.w * inv);
        *(uint4*)(Xo + (size_t)(bB * S_ + s0 + r) * HID_ + h * 64 + cg) = ov;
    }
}

// ---------------------------------------------------------------------------
// attn_B: recompute scores, apply pm + inv rowsum, write normalized attn.
// 64-row q-tile, 512 thr, 2 CTAs/SM.
// ---------------------------------------------------------------------------
#define BB_Q    0u
#define BB_K(s) (9216u + (s) * 18432u)
#define ATTNB_SMEM (9216 + 3 * 18432 + 16)

__global__ void __launch_bounds__(512, 2)
attn_B(const __half* __restrict__ Qh, const __half* __restrict__ Kh,
       const uint32_t* __restrict__ pm, const float* __restrict__ rowinv,
       float* __restrict__ attn)
{
    extern __shared__ char smg[];
    const uint32_t sb = sptr(smg);

    const int tid = threadIdx.x, lane = tid & 31, w = tid >> 5;
    const int g = lane >> 2, tg = lane & 3;
    const int wm = w & 3, wn = w >> 2;
    const int z = blockIdx.y, strip = blockIdx.x;
    const int bB = z >> 3, h = z & 7;
    const int s0 = strip * 64;

    const __half* Qsrc = Qh + (size_t)(bB * S_ + s0) * HID_ + h * 64;
    const __half* Ksrc = Kh + (size_t)(bB * S_) * HID_ + h * 64;

    auto loadK = [&](int chunk, int st) {
        const int kb = chunk * 128;
        #pragma unroll
        for (int j = 0; j < 2; j++) {
            int idx = tid + j * 512;
            int r = idx >> 3, c16 = idx & 7;
            cp16(sb + BB_K(st) + (uint32_t)r * 144u + (uint32_t)c16 * 16u,
                 Ksrc + (size_t)(kb + r) * HID_ + c16 * 8);
        }
        asm volatile("cp.async.commit_group;");
    };

    {
        int r = tid >> 3, c16 = tid & 7;
        cp16(sb + BB_Q + (uint32_t)r * 144u + (uint32_t)c16 * 16u,
             Qsrc + (size_t)r * HID_ + c16 * 8);
    }
    loadK(0, 0);
    loadK(1, 1);
    asm volatile("cp.async.wait_group 1;");
    __syncthreads();

    const __half* Qs = (const __half*)(smg + BB_Q);
    unsigned qa[4][4];
    #pragma unroll
    for (int ks = 0; ks < 4; ks++) {
        const __half* qr0 = Qs + (wm * 16 + g) * 72 + ks * 16 + 2 * tg;
        const __half* qr1 = qr0 + 8 * 72;
        qa[ks][0] = *(const uint32_t*)qr0;
        qa[ks][1] = *(const uint32_t*)qr1;
        qa[ks][2] = *(const uint32_t*)(qr0 + 8);
        qa[ks][3] = *(const uint32_t*)(qr1 + 8);
    }

    const int rowA = s0 + wm * 16 + g;
    const int rA = bB * S_ + rowA;
    const float invA = __ldg(rowinv + (size_t)z * S_ + rowA);
    const float invB = __ldg(rowinv + (size_t)z * S_ + rowA + 8);
    const size_t arowA = ((size_t)z * S_ + rowA) * S_;
    const size_t arowB = arowA + 8 * S_;

    for (int it = 0; it < 16; it++) {
        const int kb = it * 128;
        const int st = it % 3;

        const uint32_t wa = __ldg(pm + (uint32_t)rA * 64u + it * 4 + wn);
        const uint32_t wb = __ldg(pm + (uint32_t)(rA + 8) * 64u + it * 4 + wn);

        if (it > 0) {
            if (it < 15) asm volatile("cp.async.wait_group 1;");
            else         asm volatile("cp.async.wait_group 0;");
            __syncthreads();
        }
        if (it + 2 < 16) loadK(it + 2, (it + 2) % 3);

        const __half* Ks = (const __half*)(smg + BB_K(st));

        float c[4][4] = {};
        #pragma unroll
        for (int ks = 0; ks < 4; ks++) {
            #pragma unroll
            for (int nt = 0; nt < 4; nt++) {
                const __half* kp = Ks + (wn * 32 + nt * 8 + g) * 72 + ks * 16 + 2 * tg;
                unsigned b[2];
                b[0] = *(const uint32_t*)kp;
                b[1] = *(const uint32_t*)(kp + 8);
                mmah(c[nt], qa[ks], b);
            }
        }

        #pragma unroll
        for (int nt = 0; nt < 4; nt++) {
            int sh = nt * 8 + 2 * tg;
            int cg = kb + wn * 32 + sh;
            float p0 = ((wa >> sh) & 1u)       ? __expf(c[nt][0]) * invA : 0.f;
            float p1 = ((wa >> (sh + 1)) & 1u) ? __expf(c[nt][1]) * invA : 0.f;
            float p2 = ((wb >> sh) & 1u)       ? __expf(c[nt][2]) * invB : 0.f;
            float p3 = ((wb >> (sh + 1)) & 1u) ? __expf(c[nt][3]) * invB : 0.f;
            *(float2*)(attn + arowA + cg) = make_float2(p0, p1);
            *(float2*)(attn + arowB + cg) = make_float2(p2, p3);
        }
    }
}

// ---------------------------------------------------------------------------
// Launch
// ---------------------------------------------------------------------------
extern "C" void kernel_launch(void* const* d_in, const int* in_sizes, int n_in,
                              void* d_out, int out_size)
{
    const float* q    = (const float*)d_in[0];
    const float* k    = (const float*)d_in[1];
    const float* v    = (const float*)d_in[2];
    const int*   mask = (const int*)  d_in[3];
    const float* Wq   = (const float*)d_in[4];
    const float* bq   = (const float*)d_in[5];
    const float* Wk   = (const float*)d_in[6];
    const float* bk   = (const float*)d_in[7];
    const float* Wv   = (const float*)d_in[8];
    const float* bv   = (const float*)d_in[9];
    const float* Wo   = (const float*)d_in[10];
    const float* bo   = (const float*)d_in[11];

    float* out = (float*)d_out;

    __half *Qhp, *Khp, *Vhp, *Vtp, *Xhp;
    float *rinv, *scr;
    uint32_t* pmp;
    cudaGetSymbolAddress((void**)&Qhp, g_Qh);
    cudaGetSymbolAddress((void**)&Khp, g_Kh);
    cudaGetSymbolAddress((void**)&Vhp, g_Vh);
    cudaGetSymbolAddress((void**)&Vtp, g_Vt);
    cudaGetSymbolAddress((void**)&Xhp, g_Xh);
    cudaGetSymbolAddress((void**)&rinv, g_rowinv);
    cudaGetSymbolAddress((void**)&pmp, g_pm);
    cudaGetSymbolAddress((void**)&scr, g_attn_scratch);

    const size_t out_elems  = (size_t)M_ * HID_;
    const size_t attn_elems = (size_t)BH_ * S_ * S_;
    float* attn = ((size_t)out_size >= out_elems + attn_elems) ? out + out_elems : scr;

    cudaFuncSetAttribute(attn_A, cudaFuncAttributeMaxDynamicSharedMemorySize, ATTN_SMEM);
    cudaFuncSetAttribute(attn_B, cudaFuncAttributeMaxDynamicSharedMemorySize, ATTNB_SMEM);
    cudaFuncSetAttribute(proj_qkv, cudaFuncAttributeMaxDynamicSharedMemorySize, PJ_SMEM);
    cudaFuncSetAttribute(proj_out, cudaFuncAttributeMaxDynamicSharedMemorySize, PO_SMEM);

    ProjArgs pq{q, Wq, bq, Qhp, 0.125f};
    ProjArgs pk{k, Wk, bk, Khp, 1.0f};
    ProjArgs pv{v, Wv, bv, Vhp, 1.0f};
    proj_qkv<<<dim3(8, 32, 3), 256, PJ_SMEM>>>(pq, pk, pv);

    vtrans_pack<<<dim3(32, 16), 256>>>(Vhp, Vtp, mask, pmp);

    attn_A<<<dim3(32, 16), 512, ATTN_SMEM>>>(Qhp, Khp, Vtp, pmp, rinv, Xhp);

    attn_B<<<dim3(32, 16), 512, ATTNB_SMEM>>>(Qhp, Khp, pmp, rinv, attn);

    proj_out<<<dim3(8, 32), 256, PO_SMEM>>>(Xhp, Wo, bo, out);
}

// round 11
// speedup vs baseline: 1.0798x; 1.0798x over previous
#include <cuda_runtime.h>
#include <cuda_fp16.h>
#include <math.h>
#include <stdint.h>

#define B_    2
#define S_    2048
#define HID_  512
#define H_    8
#define BH_   16
#define M_    4096

// Scratch (device globals; no allocation allowed)
__device__ __align__(256) __half g_Qh[M_ * HID_];
__device__ __align__(256) __half g_Kh[M_ * HID_];
__device__ __align__(256) __half g_Vh[M_ * HID_];
__device__ __align__(256) __half g_Vt[BH_ * 64 * S_];   // [z][d][s]
__device__ __align__(256) __half g_Xh[M_ * HID_];
__device__ __align__(256) __half g_Wh[4 * HID_ * HID_]; // fp16 Wq,Wk,Wv,Wo
__device__ float g_rowinv[BH_ * S_];
__device__ uint32_t g_pm[M_ * 64];                      // packed mask bits, 1MB
__device__ float g_attn_scratch[(size_t)BH_ * S_ * S_];

// ---------------------------------------------------------------------------
// helpers
// ---------------------------------------------------------------------------
__device__ __forceinline__ unsigned f2h2(float a, float b) {
    __half2 h = __floats2half2_rn(a, b);
    return *(unsigned*)&h;
}
__device__ __forceinline__ unsigned f2h2v(float2 v) { return f2h2(v.x, v.y); }

__device__ __forceinline__ void mmah(float c[4], const unsigned a[4], const unsigned b[2]) {
    asm volatile(
        "mma.sync.aligned.m16n8k16.row.col.f32.f16.f16.f32 "
        "{%0,%1,%2,%3},{%4,%5,%6,%7},{%8,%9},{%0,%1,%2,%3};"
        : "+f"(c[0]), "+f"(c[1]), "+f"(c[2]), "+f"(c[3])
        : "r"(a[0]), "r"(a[1]), "r"(a[2]), "r"(a[3]),
          "r"(b[0]), "r"(b[1]));
}

__device__ __forceinline__ void cp16(uint32_t saddr, const void* g) {
    asm volatile("cp.async.cg.shared.global [%0], [%1], 16;" :: "r"(saddr), "l"(g));
}
__device__ __forceinline__ uint32_t sptr(const void* p) {
    return (uint32_t)__cvta_generic_to_shared(p);
}

// ---------------------------------------------------------------------------
// Weight pre-convert: 4 x [512,512] fp32 -> fp16
// ---------------------------------------------------------------------------
__global__ void __launch_bounds__(256)
wcvt(const float* __restrict__ Wq, const float* __restrict__ Wk,
     const float* __restrict__ Wv, const float* __restrict__ Wo,
     __half* __restrict__ Wh)
{
    int idx = (blockIdx.x * 256 + threadIdx.x) * 4;
    const float* s = (idx < 262144) ? Wq
                   : (idx < 524288) ? Wk
                   : (idx < 786432) ? Wv : Wo;
    float4 v = *(const float4*)(s + (idx & 262143));
    __half2 h0 = __floats2half2_rn(v.x, v.y);
    __half2 h1 = __floats2half2_rn(v.z, v.w);
    *(uint2*)(Wh + idx) = make_uint2(*(unsigned*)&h0, *(unsigned*)&h1);
}

// ---------------------------------------------------------------------------
// QKV projection (fp32 X, fp16 W, fp16 out): Y = (X @ W^T + b) * scale
// 128m x 64n, 32-k x3 stages, 2 CTAs/SM.
// ---------------------------------------------------------------------------
struct ProjArgs { const float* X; const __half* W; const float* b; __half* Yh; float scale; };

#define PJ_STAGE 23552
#define PJ_A(s) ((s) * PJ_STAGE)
#define PJ_W(s) ((s) * PJ_STAGE + 18432)
#define PJ_SMEM (3 * PJ_STAGE)

__global__ void __launch_bounds__(256, 2)
proj_qkv(ProjArgs a0, ProjArgs a1, ProjArgs a2)
{
    const ProjArgs& A_ = (blockIdx.z == 0) ? a0 : (blockIdx.z == 1) ? a1 : a2;
    const float* __restrict__ Xg = A_.X;
    const __half* __restrict__ Wg = A_.W;
    const float* __restrict__ bias = A_.b;

    extern __shared__ char psm[];
    const uint32_t sb = sptr(psm);

    const int tid = threadIdx.x;
    const int lane = tid & 31, wid = tid >> 5;
    const int g = lane >> 2, tg = lane & 3;
    const int wm = wid & 3, wn = wid >> 2;
    const int m0 = blockIdx.y * 128, n0 = blockIdx.x * 64;

    auto stage = [&](int k0, int s) {
        #pragma unroll
        for (int j = 0; j < 4; j++) {
            int lin = tid + j * 256;
            int r = lin >> 3, c4 = lin & 7;
            cp16(sb + PJ_A(s) + (uint32_t)r * 144u + (uint32_t)c4 * 16u,
                 Xg + (size_t)(m0 + r) * 512 + k0 + c4 * 4);
        }
        {
            int r = tid >> 2, c16 = tid & 3;
            cp16(sb + PJ_W(s) + (uint32_t)r * 80u + (uint32_t)c16 * 16u,
                 Wg + (size_t)(n0 + r) * 512 + k0 + c16 * 8);
        }
        asm volatile("cp.async.commit_group;");
    };

    float acc[2][4][4] = {};

    stage(0, 0);
    stage(32, 1);
    for (int t = 0; t < 16; t++) {
        if (t < 15) asm volatile("cp.async.wait_group 1;");
        else        asm volatile("cp.async.wait_group 0;");
        __syncthreads();
        if (t + 2 < 16) stage((t + 2) * 32, (t + 2) % 3);

        const float* As = (const float*)(psm + PJ_A(t % 3));
        const __half* Ws = (const __half*)(psm + PJ_W(t % 3));

        #pragma unroll
        for (int ks = 0; ks < 2; ks++) {
            unsigned af[2][4], bf[4][2];
            #pragma unroll
            for (int mi = 0; mi < 2; mi++) {
                const float* b0 = &As[(wm * 32 + mi * 16 + g) * 36 + ks * 16 + 2 * tg];
                const float* b1 = b0 + 8 * 36;
                af[mi][0] = f2h2v(*(const float2*)b0);
                af[mi][1] = f2h2v(*(const float2*)b1);
                af[mi][2] = f2h2v(*(const float2*)(b0 + 8));
                af[mi][3] = f2h2v(*(const float2*)(b1 + 8));
            }
            #pragma unroll
            for (int ni = 0; ni < 4; ni++) {
                const __half* bb = &Ws[(wn * 32 + ni * 8 + g) * 40 + ks * 16 + 2 * tg];
                bf[ni][0] = *(const uint32_t*)bb;
                bf[ni][1] = *(const uint32_t*)(bb + 8);
            }
            #pragma unroll
            for (int mi = 0; mi < 2; mi++)
                #pragma unroll
                for (int ni = 0; ni < 4; ni++)
                    mmah(acc[mi][ni], af[mi], bf[ni]);
        }
    }

    const float scale = A_.scale;
    #pragma unroll
    for (int mi = 0; mi < 2; mi++) {
        int r0 = m0 + wm * 32 + mi * 16 + g;
        #pragma unroll
        for (int ni = 0; ni < 4; ni++) {
            int c0 = n0 + wn * 32 + ni * 8 + 2 * tg;
            float b0v = __ldg(bias + c0), b1v = __ldg(bias + c0 + 1);
            __half2 h0 = __floats2half2_rn((acc[mi][ni][0] + b0v) * scale,
                                           (acc[mi][ni][1] + b1v) * scale);
            __half2 h1 = __floats2half2_rn((acc[mi][ni][2] + b0v) * scale,
                                           (acc[mi][ni][3] + b1v) * scale);
            *(__half2*)(A_.Yh + (size_t)r0 * 512 + c0) = h0;
            *(__half2*)(A_.Yh + (size_t)(r0 + 8) * 512 + c0) = h1;
        }
    }
}

// ---------------------------------------------------------------------------
// Output projection (fp16 X, fp16 W, fp32 out), 3 CTAs/SM.
// ---------------------------------------------------------------------------
#define PO_STAGE 15360
#define PO_X(s) ((s) * PO_STAGE)
#define PO_W(s) ((s) * PO_STAGE + 10240)
#define PO_SMEM (3 * PO_STAGE)

__global__ void __launch_bounds__(256, 3)
proj_out(const __half* __restrict__ Xg, const __half* __restrict__ Wg,
         const float* __restrict__ bias, float* __restrict__ Y)
{
    extern __shared__ char posm[];
    const uint32_t sb = sptr(posm);

    const int tid = threadIdx.x;
    const int lane = tid & 31, wid = tid >> 5;
    const int g = lane >> 2, tg = lane & 3;
    const int wm = wid & 3, wn = wid >> 2;
    const int m0 = blockIdx.y * 128, n0 = blockIdx.x * 64;

    auto stage = [&](int k0, int s) {
        #pragma unroll
        for (int j = 0; j < 2; j++) {
            int lin = tid + j * 256;
            int r = lin >> 2, c16 = lin & 3;
            cp16(sb + PO_X(s) + (uint32_t)r * 80u + (uint32_t)c16 * 16u,
                 Xg + (size_t)(m0 + r) * 512 + k0 + c16 * 8);
        }
        {
            int r = tid >> 2, c16 = tid & 3;
            cp16(sb + PO_W(s) + (uint32_t)r * 80u + (uint32_t)c16 * 16u,
                 Wg + (size_t)(n0 + r) * 512 + k0 + c16 * 8);
        }
        asm volatile("cp.async.commit_group;");
    };

    float acc[2][4][4] = {};

    stage(0, 0);
    stage(32, 1);
    for (int t = 0; t < 16; t++) {
        if (t < 15) asm volatile("cp.async.wait_group 1;");
        else        asm volatile("cp.async.wait_group 0;");
        __syncthreads();
        if (t + 2 < 16) stage((t + 2) * 32, (t + 2) % 3);

        const __half* Xs = (const __half*)(posm + PO_X(t % 3));
        const __half* Ws = (const __half*)(posm + PO_W(t % 3));

        #pragma unroll
        for (int ks = 0; ks < 2; ks++) {
            unsigned af[2][4], bf[4][2];
            #pragma unroll
            for (int mi = 0; mi < 2; mi++) {
                const __half* x0 = &Xs[(wm * 32 + mi * 16 + g) * 40 + ks * 16 + 2 * tg];
                const __half* x1 = x0 + 8 * 40;
                af[mi][0] = *(const uint32_t*)x0;
                af[mi][1] = *(const uint32_t*)x1;
                af[mi][2] = *(const uint32_t*)(x0 + 8);
                af[mi][3] = *(const uint32_t*)(x1 + 8);
            }
            #pragma unroll
            for (int ni = 0; ni < 4; ni++) {
                const __half* bb = &Ws[(wn * 32 + ni * 8 + g) * 40 + ks * 16 + 2 * tg];
                bf[ni][0] = *(const uint32_t*)bb;
                bf[ni][1] = *(const uint32_t*)(bb + 8);
            }
            #pragma unroll
            for (int mi = 0; mi < 2; mi++)
                #pragma unroll
                for (int ni = 0; ni < 4; ni++)
                    mmah(acc[mi][ni], af[mi], bf[ni]);
        }
    }

    #pragma unroll
    for (int mi = 0; mi < 2; mi++) {
        int r0 = m0 + wm * 32 + mi * 16 + g;
        #pragma unroll
        for (int ni = 0; ni < 4; ni++) {
            int c0 = n0 + wn * 32 + ni * 8 + 2 * tg;
            float b0v = __ldg(bias + c0), b1v = __ldg(bias + c0 + 1);
            *(float2*)(Y + (size_t)r0 * 512 + c0) =
                make_float2(acc[mi][ni][0] + b0v, acc[mi][ni][1] + b1v);
            *(float2*)(Y + (size_t)(r0 + 8) * 512 + c0) =
                make_float2(acc[mi][ni][2] + b0v, acc[mi][ni][3] + b1v);
        }
    }
}

// ---------------------------------------------------------------------------
// vtrans + mask pack: Vh [b,s,hid] -> Vt [z][d][s]; mask -> pm bits.
// ---------------------------------------------------------------------------
__global__ void __launch_bounds__(256)
vtrans_pack(const __half* __restrict__ Vh, __half* __restrict__ Vt,
            const int* __restrict__ mask, uint32_t* __restrict__ pm)
{
    __shared__ __half ts[64 * 72];
    const int tid = threadIdx.x;
    const int z = blockIdx.y, bB = z >> 3, h = z & 7;
    const int s0 = blockIdx.x * 64;

    // mask pack: this block handles 512 pm words (2 per thread)
    {
        int base = (z * 32 + blockIdx.x) * 512 + tid * 2;
        #pragma unroll
        for (int w = 0; w < 2; w++) {
            int widx = base + w;
            int row = widx >> 6, wrd = widx & 63;
            const int4* mp = (const int4*)(mask + (size_t)row * 2048 + wrd * 32);
            uint32_t u = 0;
            #pragma unroll
            for (int j = 0; j < 8; j++) {
                int4 m = __ldg(mp + j);
                u |= (m.x != 0 ? 1u : 0u) << (j * 4);
                u |= (m.y != 0 ? 1u : 0u) << (j * 4 + 1);
                u |= (m.z != 0 ? 1u : 0u) << (j * 4 + 2);
                u |= (m.w != 0 ? 1u : 0u) << (j * 4 + 3);
            }
            pm[widx] = u;
        }
    }

    #pragma unroll
    for (int j = 0; j < 8; j++) {
        int lin = tid + j * 256;
        int s = lin >> 5, du = lin & 31;
        *(uint32_t*)(ts + s * 72 + du * 2) =
            *(const uint32_t*)(Vh + (size_t)(bB * S_ + s0 + s) * HID_ + h * 64 + du * 2);
    }
    __syncthreads();
    #pragma unroll
    for (int j = 0; j < 8; j++) {
        int lin = tid + j * 256;
        int d = lin >> 5, su = lin & 31;
        __half2 o = __halves2half2(ts[(2 * su) * 72 + d], ts[(2 * su + 1) * 72 + d]);
        *(__half2*)(Vt + ((size_t)z * 64 + d) * S_ + s0 + su * 2) = o;
    }
}

// ---------------------------------------------------------------------------
// attn_A: scores+exp -> rowsum + PV (register P). pm mask w/ all-ones fast path.
// Outputs rowinv + Xh (fp16). No attn write.
// ---------------------------------------------------------------------------
#define SMB_Q    0u
#define SMB_K(s) (9216u + (s) * 18432u)
#define SMB_V(s) (64512u + (s) * 17408u)
#define SMB_RS   116736u
#define ATTN_SMEM (117008 + 16)

__global__ void __launch_bounds__(512, 1)
attn_A(const __half* __restrict__ Qh, const __half* __restrict__ Kh,
       const __half* __restrict__ Vtg, const uint32_t* __restrict__ pm,
       float* __restrict__ rowinv, __half* __restrict__ Xo)
{
    extern __shared__ char smg[];
    const uint32_t sb = sptr(smg);

    const int tid = threadIdx.x, lane = tid & 31, w = tid >> 5;
    const int g = lane >> 2, tg = lane & 3;
    const int wm = w & 3, wn = w >> 2;
    const int z = blockIdx.y, strip = blockIdx.x;
    const int bB = z >> 3, h = z & 7;
    const int s0 = strip * 64;

    float* rows = (float*)(smg + SMB_RS);
    if (tid < 64) rows[tid] = 0.f;

    const __half* Qsrc = Qh + (size_t)(bB * S_ + s0) * HID_ + h * 64;
    const __half* Ksrc = Kh + (size_t)(bB * S_) * HID_ + h * 64;
    const __half* Vsrc = Vtg + (size_t)z * 64 * S_;

    auto loadKV = [&](int chunk, int st) {
        const int kb = chunk * 128;
        #pragma unroll
        for (int j = 0; j < 2; j++) {
            int idx = tid + j * 512;
            int r = idx >> 3, c16 = idx & 7;
            cp16(sb + SMB_K(st) + (uint32_t)r * 144u + (uint32_t)c16 * 16u,
                 Ksrc + (size_t)(kb + r) * HID_ + c16 * 8);
        }
        #pragma unroll
        for (int j = 0; j < 2; j++) {
            int idx = tid + j * 512;
            int d = idx >> 4, c16 = idx & 15;
            cp16(sb + SMB_V(st) + (uint32_t)d * 272u + (uint32_t)c16 * 16u,
                 Vsrc + (size_t)d * S_ + kb + c16 * 8);
        }
        asm volatile("cp.async.commit_group;");
    };

    {
        int r = tid >> 3, c16 = tid & 7;
        cp16(sb + SMB_Q + (uint32_t)r * 144u + (uint32_t)c16 * 16u,
             Qsrc + (size_t)r * HID_ + c16 * 8);
    }
    loadKV(0, 0);
    loadKV(1, 1);
    asm volatile("cp.async.wait_group 1;");
    __syncthreads();

    const __half* Qs = (const __half*)(smg + SMB_Q);
    unsigned qa[4][4];
    #pragma unroll
    for (int ks = 0; ks < 4; ks++) {
        const __half* qr0 = Qs + (wm * 16 + g) * 72 + ks * 16 + 2 * tg;
        const __half* qr1 = qr0 + 8 * 72;
        qa[ks][0] = *(const uint32_t*)qr0;
        qa[ks][1] = *(const uint32_t*)qr1;
        qa[ks][2] = *(const uint32_t*)(qr0 + 8);
        qa[ks][3] = *(const uint32_t*)(qr1 + 8);
    }

    float pvacc[8][4] = {};
    float rsA = 0.f, rsB = 0.f;

    const int rA = bB * S_ + s0 + wm * 16 + g;   // pm row index

    for (int it = 0; it < 16; it++) {
        const int st = it % 3;

        const uint32_t wa = __ldg(pm + (uint32_t)rA * 64u + it * 4 + wn);
        const uint32_t wb = __ldg(pm + (uint32_t)(rA + 8) * 64u + it * 4 + wn);

        if (it > 0) {
            if (it < 15) asm volatile("cp.async.wait_group 1;");
            else         asm volatile("cp.async.wait_group 0;");
            __syncthreads();
        }
        if (it + 2 < 16) loadKV(it + 2, (it + 2) % 3);

        const __half* Ks = (const __half*)(smg + SMB_K(st));
        const __half* Vs = (const __half*)(smg + SMB_V(st));

        float c[4][4] = {};
        #pragma unroll
        for (int ks = 0; ks < 4; ks++) {
            #pragma unroll
            for (int nt = 0; nt < 4; nt++) {
                const __half* kp = Ks + (wn * 32 + nt * 8 + g) * 72 + ks * 16 + 2 * tg;
                unsigned b[2];
                b[0] = *(const uint32_t*)kp;
                b[1] = *(const uint32_t*)(kp + 8);
                mmah(c[nt], qa[ks], b);
            }
        }

        float p[4][4];
        #pragma unroll
        for (int nt = 0; nt < 4; nt++) {
            p[nt][0] = __expf(c[nt][0]);
            p[nt][1] = __expf(c[nt][1]);
            p[nt][2] = __expf(c[nt][2]);
            p[nt][3] = __expf(c[nt][3]);
        }
        if ((wa & wb) != 0xFFFFFFFFu) {   // masked slow path
            #pragma unroll
            for (int nt = 0; nt < 4; nt++) {
                int sh = nt * 8 + 2 * tg;
                if (!((wa >> sh) & 1u))       p[nt][0] = 0.f;
                if (!((wa >> (sh + 1)) & 1u)) p[nt][1] = 0.f;
                if (!((wb >> sh) & 1u))       p[nt][2] = 0.f;
                if (!((wb >> (sh + 1)) & 1u)) p[nt][3] = 0.f;
            }
        }
        #pragma unroll
        for (int nt = 0; nt < 4; nt++) {
            rsA += p[nt][0] + p[nt][1];
            rsB += p[nt][2] + p[nt][3];
        }

        unsigned pa[2][4];
        #pragma unroll
        for (int k2 = 0; k2 < 2; k2++) {
            pa[k2][0] = f2h2(p[2 * k2][0], p[2 * k2][1]);
            pa[k2][1] = f2h2(p[2 * k2][2], p[2 * k2][3]);
            pa[k2][2] = f2h2(p[2 * k2 + 1][0], p[2 * k2 + 1][1]);
            pa[k2][3] = f2h2(p[2 * k2 + 1][2], p[2 * k2 + 1][3]);
        }

        #pragma unroll
        for (int nt2 = 0; nt2 < 8; nt2++) {
            #pragma unroll
            for (int k2 = 0; k2 < 2; k2++) {
                const __half* vp = Vs + (nt2 * 8 + g) * 136 + wn * 32 + k2 * 16 + 2 * tg;
                unsigned b[2];
                b[0] = *(const uint32_t*)vp;
                b[1] = *(const uint32_t*)(vp + 8);
                mmah(pvacc[nt2], pa[k2], b);
            }
        }
    }

    rsA += __shfl_xor_sync(0xffffffffu, rsA, 1);
    rsA += __shfl_xor_sync(0xffffffffu, rsA, 2);
    rsB += __shfl_xor_sync(0xffffffffu, rsB, 1);
    rsB += __shfl_xor_sync(0xffffffffu, rsB, 2);
    if (tg == 0) {
        atomicAdd(&rows[wm * 16 + g    ], rsA);
        atomicAdd(&rows[wm * 16 + g + 8], rsB);
    }
    __syncthreads();

    if (tid < 64) {
        float inv = 1.0f / rows[tid];
        rows[tid] = inv;
        rowinv[(size_t)z * S_ + s0 + tid] = inv;
    }

    // PV cross-warp reduction: 4 disjoint areas, no atomics
    const uint32_t scrOff[4] = { SMB_V(0), SMB_V(1), SMB_V(2), SMB_K(2) };
    {
        float* sw = (float*)(smg + scrOff[wn]);
        #pragma unroll
        for (int nt2 = 0; nt2 < 8; nt2++) {
            int col = nt2 * 8 + 2 * tg;
            *(float2*)&sw[(wm * 16 + g    ) * 64 + col] =
                make_float2(pvacc[nt2][0], pvacc[nt2][1]);
            *(float2*)&sw[(wm * 16 + g + 8) * 64 + col] =
                make_float2(pvacc[nt2][2], pvacc[nt2][3]);
        }
    }
    __syncthreads();

    {
        int r = tid >> 3, cg = (tid & 7) * 8;
        float4 s0v = make_float4(0, 0, 0, 0), s1v = make_float4(0, 0, 0, 0);
        #pragma unroll
        for (int ww = 0; ww < 4; ww++) {
            const float* sw = (const float*)(smg + scrOff[ww]);
            float4 u0 = *(const float4*)&sw[r * 64 + cg];
            float4 u1 = *(const float4*)&sw[r * 64 + cg + 4];
            s0v.x += u0.x; s0v.y += u0.y; s0v.z += u0.z; s0v.w += u0.w;
            s1v.x += u1.x; s1v.y += u1.y; s1v.z += u1.z; s1v.w += u1.w;
        }
        float inv = rows[r];
        uint4 ov;
        ov.x = f2h2(s0v.x * inv, s0v.y * inv);
        ov.y = f2h2(s0v.z * inv, s0v.w * inv);
        ov.z = f2h2(s1v.x * inv, s1v.y * inv);
        ov.w = f2h2(s1v.z * inv, s1v.w * inv);
        *(uint4*)(Xo + (size_t)(bB * S_ + s0 + r) * HID_ + h * 64 + cg) = ov;
    }
}

// ---------------------------------------------------------------------------
// attn_B: recompute scores, apply pm (fast path) + inv rowsum, write attn.
// 64-row q-tile, 512 thr, 2 CTAs/SM.
// ---------------------------------------------------------------------------
#define BB_Q    0u
#define BB_K(s) (9216u + (s) * 18432u)
#define ATTNB_SMEM (9216 + 3 * 18432 + 16)

__global__ void __launch_bounds__(512, 2)
attn_B(const __half* __restrict__ Qh, const __half* __restrict__ Kh,
       const uint32_t* __restrict__ pm, const float* __restrict__ rowinv,
       float* __restrict__ attn)
{
    extern __shared__ char smg[];
    const uint32_t sb = sptr(smg);

    const int tid = threadIdx.x, lane = tid & 31, w = tid >> 5;
    const int g = lane >> 2, tg = lane & 3;
    const int wm = w & 3, wn = w >> 2;
    const int z = blockIdx.y, strip = blockIdx.x;
    const int bB = z >> 3, h = z & 7;
    const int s0 = strip * 64;

    const __half* Qsrc = Qh + (size_t)(bB * S_ + s0) * HID_ + h * 64;
    const __half* Ksrc = Kh + (size_t)(bB * S_) * HID_ + h * 64;

    auto loadK = [&](int chunk, int st) {
        const int kb = chunk * 128;
        #pragma unroll
        for (int j = 0; j < 2; j++) {
            int idx = tid + j * 512;
            int r = idx >> 3, c16 = idx & 7;
            cp16(sb + BB_K(st) + (uint32_t)r * 144u + (uint32_t)c16 * 16u,
                 Ksrc + (size_t)(kb + r) * HID_ + c16 * 8);
        }
        asm volatile("cp.async.commit_group;");
    };

    {
        int r = tid >> 3, c16 = tid & 7;
        cp16(sb + BB_Q + (uint32_t)r * 144u + (uint32_t)c16 * 16u,
             Qsrc + (size_t)r * HID_ + c16 * 8);
    }
    loadK(0, 0);
    loadK(1, 1);
    asm volatile("cp.async.wait_group 1;");
    __syncthreads();

    const __half* Qs = (const __half*)(smg + BB_Q);
    unsigned qa[4][4];
    #pragma unroll
    for (int ks = 0; ks < 4; ks++) {
        const __half* qr0 = Qs + (wm * 16 + g) * 72 + ks * 16 + 2 * tg;
        const __half* qr1 = qr0 + 8 * 72;
        qa[ks][0] = *(const uint32_t*)qr0;
        qa[ks][1] = *(const uint32_t*)qr1;
        qa[ks][2] = *(const uint32_t*)(qr0 + 8);
        qa[ks][3] = *(const uint32_t*)(qr1 + 8);
    }

    const int rowA = s0 + wm * 16 + g;
    const int rA = bB * S_ + rowA;
    const float invA = __ldg(rowinv + (size_t)z * S_ + rowA);
    const float invB = __ldg(rowinv + (size_t)z * S_ + rowA + 8);
    const size_t arowA = ((size_t)z * S_ + rowA) * S_;
    const size_t arowB = arowA + 8 * S_;

    for (int it = 0; it < 16; it++) {
        const int kb = it * 128;
        const int st = it % 3;

        const uint32_t wa = __ldg(pm + (uint32_t)rA * 64u + it * 4 + wn);
        const uint32_t wb = __ldg(pm + (uint32_t)(rA + 8) * 64u + it * 4 + wn);

        if (it > 0) {
            if (it < 15) asm volatile("cp.async.wait_group 1;");
            else         asm volatile("cp.async.wait_group 0;");
            __syncthreads();
        }
        if (it + 2 < 16) loadK(it + 2, (it + 2) % 3);

        const __half* Ks = (const __half*)(smg + BB_K(st));

        float c[4][4] = {};
        #pragma unroll
        for (int ks = 0; ks < 4; ks++) {
            #pragma unroll
            for (int nt = 0; nt < 4; nt++) {
                const __half* kp = Ks + (wn * 32 + nt * 8 + g) * 72 + ks * 16 + 2 * tg;
                unsigned b[2];
                b[0] = *(const uint32_t*)kp;
                b[1] = *(const uint32_t*)(kp + 8);
                mmah(c[nt], qa[ks], b);
            }
        }

        float p[4][4];
        #pragma unroll
        for (int nt = 0; nt < 4; nt++) {
            p[nt][0] = __expf(c[nt][0]) * invA;
            p[nt][1] = __expf(c[nt][1]) * invA;
            p[nt][2] = __expf(c[nt][2]) * invB;
            p[nt][3] = __expf(c[nt][3]) * invB;
        }
        if ((wa & wb) != 0xFFFFFFFFu) {   // masked slow path
            #pragma unroll
            for (int nt = 0; nt < 4; nt++) {
                int sh = nt * 8 + 2 * tg;
                if (!((wa >> sh) & 1u))       p[nt][0] = 0.f;
                if (!((wa >> (sh + 1)) & 1u)) p[nt][1] = 0.f;
                if (!((wb >> sh) & 1u))       p[nt][2] = 0.f;
                if (!((wb >> (sh + 1)) & 1u)) p[nt][3] = 0.f;
            }
        }
        #pragma unroll
        for (int nt = 0; nt < 4; nt++) {
            int cg = kb + wn * 32 + nt * 8 + 2 * tg;
            *(float2*)(attn + arowA + cg) = make_float2(p[nt][0], p[nt][1]);
            *(float2*)(attn + arowB + cg) = make_float2(p[nt][2], p[nt][3]);
        }
    }
}

// ---------------------------------------------------------------------------
// Launch
// ---------------------------------------------------------------------------
extern "C" void kernel_launch(void* const* d_in, const int* in_sizes, int n_in,
                              void* d_out, int out_size)
{
    const float* q    = (const float*)d_in[0];
    const float* k    = (const float*)d_in[1];
    const float* v    = (const float*)d_in[2];
    const int*   mask = (const int*)  d_in[3];
    const float* Wq   = (const float*)d_in[4];
    const float* bq   = (const float*)d_in[5];
    const float* Wk   = (const float*)d_in[6];
    const float* bk   = (const float*)d_in[7];
    const float* Wv   = (const float*)d_in[8];
    const float* bv   = (const float*)d_in[9];
    const float* Wo   = (const float*)d_in[10];
    const float* bo   = (const float*)d_in[11];

    float* out = (float*)d_out;

    __half *Qhp, *Khp, *Vhp, *Vtp, *Xhp, *Whp;
    float *rinv, *scr;
    uint32_t* pmp;
    cudaGetSymbolAddress((void**)&Qhp, g_Qh);
    cudaGetSymbolAddress((void**)&Khp, g_Kh);
    cudaGetSymbolAddress((void**)&Vhp, g_Vh);
    cudaGetSymbolAddress((void**)&Vtp, g_Vt);
    cudaGetSymbolAddress((void**)&Xhp, g_Xh);
    cudaGetSymbolAddress((void**)&Whp, g_Wh);
    cudaGetSymbolAddress((void**)&rinv, g_rowinv);
    cudaGetSymbolAddress((void**)&pmp, g_pm);
    cudaGetSymbolAddress((void**)&scr, g_attn_scratch);

    const size_t out_elems  = (size_t)M_ * HID_;
    const size_t attn_elems = (size_t)BH_ * S_ * S_;
    float* attn = ((size_t)out_size >= out_elems + attn_elems) ? out + out_elems : scr;

    cudaFuncSetAttribute(attn_A, cudaFuncAttributeMaxDynamicSharedMemorySize, ATTN_SMEM);
    cudaFuncSetAttribute(attn_B, cudaFuncAttributeMaxDynamicSharedMemorySize, ATTNB_SMEM);
    cudaFuncSetAttribute(proj_qkv, cudaFuncAttributeMaxDynamicSharedMemorySize, PJ_SMEM);
    cudaFuncSetAttribute(proj_out, cudaFuncAttributeMaxDynamicSharedMemorySize, PO_SMEM);

    wcvt<<<1024, 256>>>(Wq, Wk, Wv, Wo, Whp);

    ProjArgs pq{q, Whp,               bq, Qhp, 0.125f};
    ProjArgs pk{k, Whp + 262144,      bk, Khp, 1.0f};
    ProjArgs pv{v, Whp + 524288,      bv, Vhp, 1.0f};
    proj_qkv<<<dim3(8, 32, 3), 256, PJ_SMEM>>>(pq, pk, pv);

    vtrans_pack<<<dim3(32, 16), 256>>>(Vhp, Vtp, mask, pmp);

    attn_A<<<dim3(32, 16), 512, ATTN_SMEM>>>(Qhp, Khp, Vtp, pmp, rinv, Xhp);

    attn_B<<<dim3(32, 16), 512, ATTNB_SMEM>>>(Qhp, Khp, pmp, rinv, attn);

    proj_out<<<dim3(8, 32), 256, PO_SMEM>>>(Xhp, Whp + 786432, bo, out);
}

// round 12
// speedup vs baseline: 1.1933x; 1.1051x over previous
#include <cuda_runtime.h>
#include <cuda_fp16.h>
#include <math.h>
#include <stdint.h>

#define B_    2
#define S_    2048
#define HID_  512
#define H_    8
#define BH_   16
#define M_    4096

// Scratch (device globals; no allocation allowed)
__device__ __align__(256) __half g_Qh[M_ * HID_];
__device__ __align__(256) __half g_Kh[M_ * HID_];
__device__ __align__(256) __half g_Vh[M_ * HID_];
__device__ __align__(256) __half g_Vt[BH_ * 64 * S_];   // [z][d][s]
__device__ __align__(256) __half g_Xh[M_ * HID_];
__device__ __align__(256) __half g_Wh[4 * HID_ * HID_]; // fp16 Wq,Wk,Wv,Wo
__device__ __align__(256) __half g_inx[3 * M_ * HID_];  // fp16 q,k,v inputs
__device__ float g_rowinv[BH_ * S_];
__device__ uint32_t g_pm[M_ * 64];                      // packed mask bits, 1MB
__device__ float g_attn_scratch[(size_t)BH_ * S_ * S_];

// ---------------------------------------------------------------------------
// helpers
// ---------------------------------------------------------------------------
__device__ __forceinline__ unsigned f2h2(float a, float b) {
    __half2 h = __floats2half2_rn(a, b);
    return *(unsigned*)&h;
}

__device__ __forceinline__ void mmah(float c[4], const unsigned a[4], const unsigned b[2]) {
    asm volatile(
        "mma.sync.aligned.m16n8k16.row.col.f32.f16.f16.f32 "
        "{%0,%1,%2,%3},{%4,%5,%6,%7},{%8,%9},{%0,%1,%2,%3};"
        : "+f"(c[0]), "+f"(c[1]), "+f"(c[2]), "+f"(c[3])
        : "r"(a[0]), "r"(a[1]), "r"(a[2]), "r"(a[3]),
          "r"(b[0]), "r"(b[1]));
}

__device__ __forceinline__ void ldsm4(uint32_t& r0, uint32_t& r1, uint32_t& r2,
                                      uint32_t& r3, uint32_t a) {
    asm volatile("ldmatrix.sync.aligned.m8n8.x4.shared.b16 {%0,%1,%2,%3}, [%4];"
                 : "=r"(r0), "=r"(r1), "=r"(r2), "=r"(r3) : "r"(a));
}

__device__ __forceinline__ void cp16(uint32_t saddr, const void* g) {
    asm volatile("cp.async.cg.shared.global [%0], [%1], 16;" :: "r"(saddr), "l"(g));
}
__device__ __forceinline__ uint32_t sptr(const void* p) {
    return (uint32_t)__cvta_generic_to_shared(p);
}

// ---------------------------------------------------------------------------
// One-time converts: weights + inputs fp32 -> fp16
// ---------------------------------------------------------------------------
__global__ void __launch_bounds__(256)
wcvt(const float* __restrict__ Wq, const float* __restrict__ Wk,
     const float* __restrict__ Wv, const float* __restrict__ Wo,
     __half* __restrict__ Wh)
{
    int idx = (blockIdx.x * 256 + threadIdx.x) * 4;
    const float* s = (idx < 262144) ? Wq
                   : (idx < 524288) ? Wk
                   : (idx < 786432) ? Wv : Wo;
    float4 v = *(const float4*)(s + (idx & 262143));
    __half2 h0 = __floats2half2_rn(v.x, v.y);
    __half2 h1 = __floats2half2_rn(v.z, v.w);
    *(uint2*)(Wh + idx) = make_uint2(*(unsigned*)&h0, *(unsigned*)&h1);
}

__global__ void __launch_bounds__(256)
xcvt(const float* __restrict__ q, const float* __restrict__ k,
     const float* __restrict__ v, __half* __restrict__ dst)
{
    int idx = (blockIdx.x * 256 + threadIdx.x) * 4;
    const float* s = (idx < 2097152) ? q : (idx < 4194304) ? k : v;
    float4 w = *(const float4*)(s + (idx & 2097151));
    __half2 h0 = __floats2half2_rn(w.x, w.y);
    __half2 h1 = __floats2half2_rn(w.z, w.w);
    *(uint2*)(dst + idx) = make_uint2(*(unsigned*)&h0, *(unsigned*)&h1);
}

// ---------------------------------------------------------------------------
// Unified projection (fp16 X, fp16 W): Y = (X @ W^T + b) * scale
// -> fp16 (Yh) or fp32 (Yf). 128m x 64n, 32-k x3 stages, 3 CTAs/SM.
// ---------------------------------------------------------------------------
struct ProjArgs { const __half* X; const __half* W; const float* b;
                  __half* Yh; float* Yf; float scale; };

#define PJ_STAGE 15360
#define PJ_X(s) ((s) * PJ_STAGE)
#define PJ_W(s) ((s) * PJ_STAGE + 10240)
#define PJ_SMEM (3 * PJ_STAGE)

__global__ void __launch_bounds__(256, 3)
proj_h(ProjArgs a0, ProjArgs a1, ProjArgs a2)
{
    const ProjArgs& A_ = (blockIdx.z == 0) ? a0 : (blockIdx.z == 1) ? a1 : a2;
    const __half* __restrict__ Xg = A_.X;
    const __half* __restrict__ Wg = A_.W;
    const float* __restrict__ bias = A_.b;

    extern __shared__ char psm[];
    const uint32_t sb = sptr(psm);

    const int tid = threadIdx.x;
    const int lane = tid & 31, wid = tid >> 5;
    const int g = lane >> 2, tg = lane & 3;
    const int wm = wid & 3, wn = wid >> 2;
    const int m0 = blockIdx.y * 128, n0 = blockIdx.x * 64;

    auto stage = [&](int k0, int s) {
        #pragma unroll
        for (int j = 0; j < 2; j++) {
            int lin = tid + j * 256;
            int r = lin >> 2, c16 = lin & 3;
            cp16(sb + PJ_X(s) + (uint32_t)r * 80u + (uint32_t)c16 * 16u,
                 Xg + (size_t)(m0 + r) * 512 + k0 + c16 * 8);
        }
        {
            int r = tid >> 2, c16 = tid & 3;
            cp16(sb + PJ_W(s) + (uint32_t)r * 80u + (uint32_t)c16 * 16u,
                 Wg + (size_t)(n0 + r) * 512 + k0 + c16 * 8);
        }
        asm volatile("cp.async.commit_group;");
    };

    float acc[2][4][4] = {};

    stage(0, 0);
    stage(32, 1);
    for (int t = 0; t < 16; t++) {
        if (t < 15) asm volatile("cp.async.wait_group 1;");
        else        asm volatile("cp.async.wait_group 0;");
        __syncthreads();
        if (t + 2 < 16) stage((t + 2) * 32, (t + 2) % 3);

        const __half* Xs = (const __half*)(psm + PJ_X(t % 3));
        const __half* Ws = (const __half*)(psm + PJ_W(t % 3));

        #pragma unroll
        for (int ks = 0; ks < 2; ks++) {
            unsigned af[2][4], bf[4][2];
            #pragma unroll
            for (int mi = 0; mi < 2; mi++) {
                const __half* x0 = &Xs[(wm * 32 + mi * 16 + g) * 40 + ks * 16 + 2 * tg];
                const __half* x1 = x0 + 8 * 40;
                af[mi][0] = *(const uint32_t*)x0;
                af[mi][1] = *(const uint32_t*)x1;
                af[mi][2] = *(const uint32_t*)(x0 + 8);
                af[mi][3] = *(const uint32_t*)(x1 + 8);
            }
            #pragma unroll
            for (int ni = 0; ni < 4; ni++) {
                const __half* bb = &Ws[(wn * 32 + ni * 8 + g) * 40 + ks * 16 + 2 * tg];
                bf[ni][0] = *(const uint32_t*)bb;
                bf[ni][1] = *(const uint32_t*)(bb + 8);
            }
            #pragma unroll
            for (int mi = 0; mi < 2; mi++)
                #pragma unroll
                for (int ni = 0; ni < 4; ni++)
                    mmah(acc[mi][ni], af[mi], bf[ni]);
        }
    }

    const float scale = A_.scale;
    #pragma unroll
    for (int mi = 0; mi < 2; mi++) {
        int r0 = m0 + wm * 32 + mi * 16 + g;
        #pragma unroll
        for (int ni = 0; ni < 4; ni++) {
            int c0 = n0 + wn * 32 + ni * 8 + 2 * tg;
            float b0v = __ldg(bias + c0), b1v = __ldg(bias + c0 + 1);
            float y00 = acc[mi][ni][0] + b0v, y01 = acc[mi][ni][1] + b1v;
            float y10 = acc[mi][ni][2] + b0v, y11 = acc[mi][ni][3] + b1v;
            if (A_.Yh) {
                *(unsigned*)(A_.Yh + (size_t)r0 * 512 + c0) = f2h2(y00 * scale, y01 * scale);
                *(unsigned*)(A_.Yh + (size_t)(r0 + 8) * 512 + c0) = f2h2(y10 * scale, y11 * scale);
            } else {
                *(float2*)(A_.Yf + (size_t)r0 * 512 + c0) = make_float2(y00, y01);
                *(float2*)(A_.Yf + (size_t)(r0 + 8) * 512 + c0) = make_float2(y10, y11);
            }
        }
    }
}

// ---------------------------------------------------------------------------
// vtrans + mask pack: Vh [b,s,hid] -> Vt [z][d][s]; mask -> pm bits.
// ---------------------------------------------------------------------------
__global__ void __launch_bounds__(256)
vtrans_pack(const __half* __restrict__ Vh, __half* __restrict__ Vt,
            const int* __restrict__ mask, uint32_t* __restrict__ pm)
{
    __shared__ __half ts[64 * 72];
    const int tid = threadIdx.x;
    const int z = blockIdx.y, bB = z >> 3, h = z & 7;
    const int s0 = blockIdx.x * 64;

    {
        int base = (z * 32 + blockIdx.x) * 512 + tid * 2;
        #pragma unroll
        for (int w = 0; w < 2; w++) {
            int widx = base + w;
            int row = widx >> 6, wrd = widx & 63;
            const int4* mp = (const int4*)(mask + (size_t)row * 2048 + wrd * 32);
            uint32_t u = 0;
            #pragma unroll
            for (int j = 0; j < 8; j++) {
                int4 m = __ldg(mp + j);
                u |= (m.x != 0 ? 1u : 0u) << (j * 4);
                u |= (m.y != 0 ? 1u : 0u) << (j * 4 + 1);
                u |= (m.z != 0 ? 1u : 0u) << (j * 4 + 2);
                u |= (m.w != 0 ? 1u : 0u) << (j * 4 + 3);
            }
            pm[widx] = u;
        }
    }

    #pragma unroll
    for (int j = 0; j < 8; j++) {
        int lin = tid + j * 256;
        int s = lin >> 5, du = lin & 31;
        *(uint32_t*)(ts + s * 72 + du * 2) =
            *(const uint32_t*)(Vh + (size_t)(bB * S_ + s0 + s) * HID_ + h * 64 + du * 2);
    }
    __syncthreads();
    #pragma unroll
    for (int j = 0; j < 8; j++) {
        int lin = tid + j * 256;
        int d = lin >> 5, su = lin & 31;
        __half2 o = __halves2half2(ts[(2 * su) * 72 + d], ts[(2 * su + 1) * 72 + d]);
        *(__half2*)(Vt + ((size_t)z * 64 + d) * S_ + s0 + su * 2) = o;
    }
}

// ---------------------------------------------------------------------------
// attn_A: scores+exp -> rowsum + PV (register P). ldmatrix fragment feeds.
// Outputs rowinv + Xh (fp16). No attn write.
// ---------------------------------------------------------------------------
#define SMB_Q    0u
#define SMB_K(s) (9216u + (s) * 18432u)
#define SMB_V(s) (64512u + (s) * 17408u)
#define SMB_RS   116736u
#define ATTN_SMEM (117008 + 16)

__global__ void __launch_bounds__(512, 1)
attn_A(const __half* __restrict__ Qh, const __half* __restrict__ Kh,
       const __half* __restrict__ Vtg, const uint32_t* __restrict__ pm,
       float* __restrict__ rowinv, __half* __restrict__ Xo)
{
    extern __shared__ char smg[];
    const uint32_t sb = sptr(smg);

    const int tid = threadIdx.x, lane = tid & 31, w = tid >> 5;
    const int g = lane >> 2, tg = lane & 3;
    const int wm = w & 3, wn = w >> 2;
    const int z = blockIdx.y, strip = blockIdx.x;
    const int bB = z >> 3, h = z & 7;
    const int s0 = strip * 64;

    float* rows = (float*)(smg + SMB_RS);
    if (tid < 64) rows[tid] = 0.f;

    const __half* Qsrc = Qh + (size_t)(bB * S_ + s0) * HID_ + h * 64;
    const __half* Ksrc = Kh + (size_t)(bB * S_) * HID_ + h * 64;
    const __half* Vsrc = Vtg + (size_t)z * 64 * S_;

    // ldmatrix lane offsets (bytes)
    const uint32_t so_sc = (uint32_t)(wn * 32 + (lane & 7)) * 144u
                         + ((lane >> 4) & 1) * 32u + ((lane >> 3) & 1) * 16u;
    const uint32_t so_pv = (uint32_t)(lane & 7) * 272u + (uint32_t)wn * 64u
                         + ((lane >> 4) & 1) * 32u + ((lane >> 3) & 1) * 16u;

    auto loadKV = [&](int chunk, int st) {
        const int kb = chunk * 128;
        #pragma unroll
        for (int j = 0; j < 2; j++) {
            int idx = tid + j * 512;
            int r = idx >> 3, c16 = idx & 7;
            cp16(sb + SMB_K(st) + (uint32_t)r * 144u + (uint32_t)c16 * 16u,
                 Ksrc + (size_t)(kb + r) * HID_ + c16 * 8);
        }
        #pragma unroll
        for (int j = 0; j < 2; j++) {
            int idx = tid + j * 512;
            int d = idx >> 4, c16 = idx & 15;
            cp16(sb + SMB_V(st) + (uint32_t)d * 272u + (uint32_t)c16 * 16u,
                 Vsrc + (size_t)d * S_ + kb + c16 * 8);
        }
        asm volatile("cp.async.commit_group;");
    };

    {
        int r = tid >> 3, c16 = tid & 7;
        cp16(sb + SMB_Q + (uint32_t)r * 144u + (uint32_t)c16 * 16u,
             Qsrc + (size_t)r * HID_ + c16 * 8);
    }
    loadKV(0, 0);
    loadKV(1, 1);
    asm volatile("cp.async.wait_group 1;");
    __syncthreads();

    const __half* Qs = (const __half*)(smg + SMB_Q);
    unsigned qa[4][4];
    #pragma unroll
    for (int ks = 0; ks < 4; ks++) {
        const __half* qr0 = Qs + (wm * 16 + g) * 72 + ks * 16 + 2 * tg;
        const __half* qr1 = qr0 + 8 * 72;
        qa[ks][0] = *(const uint32_t*)qr0;
        qa[ks][1] = *(const uint32_t*)qr1;
        qa[ks][2] = *(const uint32_t*)(qr0 + 8);
        qa[ks][3] = *(const uint32_t*)(qr1 + 8);
    }

    float pvacc[8][4] = {};
    float rsA = 0.f, rsB = 0.f;

    const int rA = bB * S_ + s0 + wm * 16 + g;   // pm row index

    for (int it = 0; it < 16; it++) {
        const int st = it % 3;

        const uint32_t wa = __ldg(pm + (uint32_t)rA * 64u + it * 4 + wn);
        const uint32_t wb = __ldg(pm + (uint32_t)(rA + 8) * 64u + it * 4 + wn);

        if (it > 0) {
            if (it < 15) asm volatile("cp.async.wait_group 1;");
            else         asm volatile("cp.async.wait_group 0;");
            __syncthreads();
        }
        if (it + 2 < 16) loadKV(it + 2, (it + 2) % 3);

        // scores via ldmatrix: 8 x4 ops
        float c[4][4] = {};
        {
            const uint32_t kbase = sb + SMB_K(st) + so_sc;
            #pragma unroll
            for (int p = 0; p < 2; p++) {
                #pragma unroll
                for (int nt = 0; nt < 4; nt++) {
                    uint32_t r0, r1, r2, r3;
                    ldsm4(r0, r1, r2, r3, kbase + (uint32_t)nt * 1152u + (uint32_t)p * 64u);
                    unsigned b0[2] = { r0, r1 }, b1[2] = { r2, r3 };
                    mmah(c[nt], qa[2 * p], b0);
                    mmah(c[nt], qa[2 * p + 1], b1);
                }
            }
        }

        float p[4][4];
        #pragma unroll
        for (int nt = 0; nt < 4; nt++) {
            p[nt][0] = __expf(c[nt][0]);
            p[nt][1] = __expf(c[nt][1]);
            p[nt][2] = __expf(c[nt][2]);
            p[nt][3] = __expf(c[nt][3]);
        }
        if ((wa & wb) != 0xFFFFFFFFu) {
            #pragma unroll
            for (int nt = 0; nt < 4; nt++) {
                int sh = nt * 8 + 2 * tg;
                if (!((wa >> sh) & 1u))       p[nt][0] = 0.f;
                if (!((wa >> (sh + 1)) & 1u)) p[nt][1] = 0.f;
                if (!((wb >> sh) & 1u))       p[nt][2] = 0.f;
                if (!((wb >> (sh + 1)) & 1u)) p[nt][3] = 0.f;
            }
        }
        #pragma unroll
        for (int nt = 0; nt < 4; nt++) {
            rsA += p[nt][0] + p[nt][1];
            rsB += p[nt][2] + p[nt][3];
        }

        unsigned pa[2][4];
        #pragma unroll
        for (int k2 = 0; k2 < 2; k2++) {
            pa[k2][0] = f2h2(p[2 * k2][0], p[2 * k2][1]);
            pa[k2][1] = f2h2(p[2 * k2][2], p[2 * k2][3]);
            pa[k2][2] = f2h2(p[2 * k2 + 1][0], p[2 * k2 + 1][1]);
            pa[k2][3] = f2h2(p[2 * k2 + 1][2], p[2 * k2 + 1][3]);
        }

        // PV via ldmatrix: 8 x4 ops
        {
            const uint32_t vbase = sb + SMB_V(st) + so_pv;
            #pragma unroll
            for (int nt2 = 0; nt2 < 8; nt2++) {
                uint32_t r0, r1, r2, r3;
                ldsm4(r0, r1, r2, r3, vbase + (uint32_t)nt2 * 2176u);
                unsigned b0[2] = { r0, r1 }, b1[2] = { r2, r3 };
                mmah(pvacc[nt2], pa[0], b0);
                mmah(pvacc[nt2], pa[1], b1);
            }
        }
    }

    rsA += __shfl_xor_sync(0xffffffffu, rsA, 1);
    rsA += __shfl_xor_sync(0xffffffffu, rsA, 2);
    rsB += __shfl_xor_sync(0xffffffffu, rsB, 1);
    rsB += __shfl_xor_sync(0xffffffffu, rsB, 2);
    if (tg == 0) {
        atomicAdd(&rows[wm * 16 + g    ], rsA);
        atomicAdd(&rows[wm * 16 + g + 8], rsB);
    }
    __syncthreads();

    if (tid < 64) {
        float inv = 1.0f / rows[tid];
        rows[tid] = inv;
        rowinv[(size_t)z * S_ + s0 + tid] = inv;
    }

    // PV cross-warp reduction: 4 disjoint areas, no atomics
    const uint32_t scrOff[4] = { SMB_V(0), SMB_V(1), SMB_V(2), SMB_K(2) };
    {
        float* sw = (float*)(smg + scrOff[wn]);
        #pragma unroll
        for (int nt2 = 0; nt2 < 8; nt2++) {
            int col = nt2 * 8 + 2 * tg;
            *(float2*)&sw[(wm * 16 + g    ) * 64 + col] =
                make_float2(pvacc[nt2][0], pvacc[nt2][1]);
            *(float2*)&sw[(wm * 16 + g + 8) * 64 + col] =
                make_float2(pvacc[nt2][2], pvacc[nt2][3]);
        }
    }
    __syncthreads();

    {
        int r = tid >> 3, cg = (tid & 7) * 8;
        float4 s0v = make_float4(0, 0, 0, 0), s1v = make_float4(0, 0, 0, 0);
        #pragma unroll
        for (int ww = 0; ww < 4; ww++) {
            const float* sw = (const float*)(smg + scrOff[ww]);
            float4 u0 = *(const float4*)&sw[r * 64 + cg];
            float4 u1 = *(const float4*)&sw[r * 64 + cg + 4];
            s0v.x += u0.x; s0v.y += u0.y; s0v.z += u0.z; s0v.w += u0.w;
            s1v.x += u1.x; s1v.y += u1.y; s1v.z += u1.z; s1v.w += u1.w;
        }
        float inv = rows[r];
        uint4 ov;
        ov.x = f2h2(s0v.x * inv, s0v.y * inv);
        ov.y = f2h2(s0v.z * inv, s0v.w * inv);
        ov.z = f2h2(s1v.x * inv, s1v.y * inv);
        ov.w = f2h2(s1v.z * inv, s1v.w * inv);
        *(uint4*)(Xo + (size_t)(bB * S_ + s0 + r) * HID_ + h * 64 + cg) = ov;
    }
}

// ---------------------------------------------------------------------------
// attn_B: recompute scores (ldmatrix feeds), pm fast path + inv rowsum,
// write normalized attn. 64-row q-tile, 512 thr, 2 CTAs/SM.
// ---------------------------------------------------------------------------
#define BB_Q    0u
#define BB_K(s) (9216u + (s) * 18432u)
#define ATTNB_SMEM (9216 + 3 * 18432 + 16)

__global__ void __launch_bounds__(512, 2)
attn_B(const __half* __restrict__ Qh, const __half* __restrict__ Kh,
       const uint32_t* __restrict__ pm, const float* __restrict__ rowinv,
       float* __restrict__ attn)
{
    extern __shared__ char smg[];
    const uint32_t sb = sptr(smg);

    const int tid = threadIdx.x, lane = tid & 31, w = tid >> 5;
    const int g = lane >> 2, tg = lane & 3;
    const int wm = w & 3, wn = w >> 2;
    const int z = blockIdx.y, strip = blockIdx.x;
    const int bB = z >> 3, h = z & 7;
    const int s0 = strip * 64;

    const __half* Qsrc = Qh + (size_t)(bB * S_ + s0) * HID_ + h * 64;
    const __half* Ksrc = Kh + (size_t)(bB * S_) * HID_ + h * 64;

    const uint32_t so_sc = (uint32_t)(wn * 32 + (lane & 7)) * 144u
                         + ((lane >> 4) & 1) * 32u + ((lane >> 3) & 1) * 16u;

    auto loadK = [&](int chunk, int st) {
        const int kb = chunk * 128;
        #pragma unroll
        for (int j = 0; j < 2; j++) {
            int idx = tid + j * 512;
            int r = idx >> 3, c16 = idx & 7;
            cp16(sb + BB_K(st) + (uint32_t)r * 144u + (uint32_t)c16 * 16u,
                 Ksrc + (size_t)(kb + r) * HID_ + c16 * 8);
        }
        asm volatile("cp.async.commit_group;");
    };

    {
        int r = tid >> 3, c16 = tid & 7;
        cp16(sb + BB_Q + (uint32_t)r * 144u + (uint32_t)c16 * 16u,
             Qsrc + (size_t)r * HID_ + c16 * 8);
    }
    loadK(0, 0);
    loadK(1, 1);
    asm volatile("cp.async.wait_group 1;");
    __syncthreads();

    const __half* Qs = (const __half*)(smg + BB_Q);
    unsigned qa[4][4];
    #pragma unroll
    for (int ks = 0; ks < 4; ks++) {
        const __half* qr0 = Qs + (wm * 16 + g) * 72 + ks * 16 + 2 * tg;
        const __half* qr1 = qr0 + 8 * 72;
        qa[ks][0] = *(const uint32_t*)qr0;
        qa[ks][1] = *(const uint32_t*)qr1;
        qa[ks][2] = *(const uint32_t*)(qr0 + 8);
        qa[ks][3] = *(const uint32_t*)(qr1 + 8);
    }

    const int rowA = s0 + wm * 16 + g;
    const int rA = bB * S_ + rowA;
    const float invA = __ldg(rowinv + (size_t)z * S_ + rowA);
    const float invB = __ldg(rowinv + (size_t)z * S_ + rowA + 8);
    const size_t arowA = ((size_t)z * S_ + rowA) * S_;
    const size_t arowB = arowA + 8 * S_;

    for (int it = 0; it < 16; it++) {
        const int kb = it * 128;
        const int st = it % 3;

        const uint32_t wa = __ldg(pm + (uint32_t)rA * 64u + it * 4 + wn);
        const uint32_t wb = __ldg(pm + (uint32_t)(rA + 8) * 64u + it * 4 + wn);

        if (it > 0) {
            if (it < 15) asm volatile("cp.async.wait_group 1;");
            else         asm volatile("cp.async.wait_group 0;");
            __syncthreads();
        }
        if (it + 2 < 16) loadK(it + 2, (it + 2) % 3);

        float c[4][4] = {};
        {
            const uint32_t kbase = sb + BB_K(st) + so_sc;
            #pragma unroll
            for (int p = 0; p < 2; p++) {
                #pragma unroll
                for (int nt = 0; nt < 4; nt++) {
                    uint32_t r0, r1, r2, r3;
                    ldsm4(r0, r1, r2, r3, kbase + (uint32_t)nt * 1152u + (uint32_t)p * 64u);
                    unsigned b0[2] = { r0, r1 }, b1[2] = { r2, r3 };
                    mmah(c[nt], qa[2 * p], b0);
                    mmah(c[nt], qa[2 * p + 1], b1);
                }
            }
        }

        float p[4][4];
        #pragma unroll
        for (int nt = 0; nt < 4; nt++) {
            p[nt][0] = __expf(c[nt][0]) * invA;
            p[nt][1] = __expf(c[nt][1]) * invA;
            p[nt][2] = __expf(c[nt][2]) * invB;
            p[nt][3] = __expf(c[nt][3]) * invB;
        }
        if ((wa & wb) != 0xFFFFFFFFu) {
            #pragma unroll
            for (int nt = 0; nt < 4; nt++) {
                int sh = nt * 8 + 2 * tg;
                if (!((wa >> sh) & 1u))       p[nt][0] = 0.f;
                if (!((wa >> (sh + 1)) & 1u)) p[nt][1] = 0.f;
                if (!((wb >> sh) & 1u))       p[nt][2] = 0.f;
                if (!((wb >> (sh + 1)) & 1u)) p[nt][3] = 0.f;
            }
        }
        #pragma unroll
        for (int nt = 0; nt < 4; nt++) {
            int cg = kb + wn * 32 + nt * 8 + 2 * tg;
            *(float2*)(attn + arowA + cg) = make_float2(p[nt][0], p[nt][1]);
            *(float2*)(attn + arowB + cg) = make_float2(p[nt][2], p[nt][3]);
        }
    }
}

// ---------------------------------------------------------------------------
// Launch
// ---------------------------------------------------------------------------
extern "C" void kernel_launch(void* const* d_in, const int* in_sizes, int n_in,
                              void* d_out, int out_size)
{
    const float* q    = (const float*)d_in[0];
    const float* k    = (const float*)d_in[1];
    const float* v    = (const float*)d_in[2];
    const int*   mask = (const int*)  d_in[3];
    const float* Wq   = (const float*)d_in[4];
    const float* bq   = (const float*)d_in[5];
    const float* Wk   = (const float*)d_in[6];
    const float* bk   = (const float*)d_in[7];
    const float* Wv   = (const float*)d_in[8];
    const float* bv   = (const float*)d_in[9];
    const float* Wo   = (const float*)d_in[10];
    const float* bo   = (const float*)d_in[11];

    float* out = (float*)d_out;

    __half *Qhp, *Khp, *Vhp, *Vtp, *Xhp, *Whp, *Xin;
    float *rinv, *scr;
    uint32_t* pmp;
    cudaGetSymbolAddress((void**)&Qhp, g_Qh);
    cudaGetSymbolAddress((void**)&Khp, g_Kh);
    cudaGetSymbolAddress((void**)&Vhp, g_Vh);
    cudaGetSymbolAddress((void**)&Vtp, g_Vt);
    cudaGetSymbolAddress((void**)&Xhp, g_Xh);
    cudaGetSymbolAddress((void**)&Whp, g_Wh);
    cudaGetSymbolAddress((void**)&Xin, g_inx);
    cudaGetSymbolAddress((void**)&rinv, g_rowinv);
    cudaGetSymbolAddress((void**)&pmp, g_pm);
    cudaGetSymbolAddress((void**)&scr, g_attn_scratch);

    const size_t out_elems  = (size_t)M_ * HID_;
    const size_t attn_elems = (size_t)BH_ * S_ * S_;
    float* attn = ((size_t)out_size >= out_elems + attn_elems) ? out + out_elems : scr;

    cudaFuncSetAttribute(attn_A, cudaFuncAttributeMaxDynamicSharedMemorySize, ATTN_SMEM);
    cudaFuncSetAttribute(attn_B, cudaFuncAttributeMaxDynamicSharedMemorySize, ATTNB_SMEM);
    cudaFuncSetAttribute(proj_h, cudaFuncAttributeMaxDynamicSharedMemorySize, PJ_SMEM);

    wcvt<<<1024, 256>>>(Wq, Wk, Wv, Wo, Whp);
    xcvt<<<6144, 256>>>(q, k, v, Xin);

    ProjArgs pq{Xin,               Whp,          bq, Qhp, nullptr, 0.125f};
    ProjArgs pk{Xin + 2097152,     Whp + 262144, bk, Khp, nullptr, 1.0f};
    ProjArgs pv{Xin + 4194304,     Whp + 524288, bv, Vhp, nullptr, 1.0f};
    proj_h<<<dim3(8, 32, 3), 256, PJ_SMEM>>>(pq, pk, pv);

    vtrans_pack<<<dim3(32, 16), 256>>>(Vhp, Vtp, mask, pmp);

    attn_A<<<dim3(32, 16), 512, ATTN_SMEM>>>(Qhp, Khp, Vtp, pmp, rinv, Xhp);

    attn_B<<<dim3(32, 16), 512, ATTNB_SMEM>>>(Qhp, Khp, pmp, rinv, attn);

    ProjArgs po{Xhp, Whp + 786432, bo, nullptr, out, 1.0f};
    proj_h<<<dim3(8, 32, 1), 256, PJ_SMEM>>>(po, po, po);
}

// round 13
// speedup vs baseline: 1.2128x; 1.0164x over previous
#include <cuda_runtime.h>
#include <cuda_fp16.h>
#include <math.h>
#include <stdint.h>

#define B_    2
#define S_    2048
#define HID_  512
#define H_    8
#define BH_   16
#define M_    4096

// Scratch (device globals; no allocation allowed)
__device__ __align__(256) __half g_Qh[M_ * HID_];
__device__ __align__(256) __half g_Kh[M_ * HID_];
__device__ __align__(256) __half g_Vh[M_ * HID_];
__device__ __align__(256) __half g_Vt[BH_ * 64 * S_];   // [z][d][s]
__device__ __align__(256) __half g_Xh[M_ * HID_];
__device__ __align__(256) __half g_Wh[4 * HID_ * HID_]; // fp16 Wq,Wk,Wv,Wo
__device__ __align__(256) __half g_inx[3 * M_ * HID_];  // fp16 q,k,v inputs
__device__ float g_rowinv[BH_ * S_];
__device__ uint32_t g_pm[M_ * 64];                      // packed mask bits, 1MB
__device__ float g_attn_scratch[(size_t)BH_ * S_ * S_];

// ---------------------------------------------------------------------------
// helpers
// ---------------------------------------------------------------------------
__device__ __forceinline__ unsigned f2h2(float a, float b) {
    __half2 h = __floats2half2_rn(a, b);
    return *(unsigned*)&h;
}

__device__ __forceinline__ void mmah(float c[4], const unsigned a[4], const unsigned b[2]) {
    asm volatile(
        "mma.sync.aligned.m16n8k16.row.col.f32.f16.f16.f32 "
        "{%0,%1,%2,%3},{%4,%5,%6,%7},{%8,%9},{%0,%1,%2,%3};"
        : "+f"(c[0]), "+f"(c[1]), "+f"(c[2]), "+f"(c[3])
        : "r"(a[0]), "r"(a[1]), "r"(a[2]), "r"(a[3]),
          "r"(b[0]), "r"(b[1]));
}

__device__ __forceinline__ void ldsm4(uint32_t& r0, uint32_t& r1, uint32_t& r2,
                                      uint32_t& r3, uint32_t a) {
    asm volatile("ldmatrix.sync.aligned.m8n8.x4.shared.b16 {%0,%1,%2,%3}, [%4];"
                 : "=r"(r0), "=r"(r1), "=r"(r2), "=r"(r3) : "r"(a));
}

__device__ __forceinline__ void cp16(uint32_t saddr, const void* g) {
    asm volatile("cp.async.cg.shared.global [%0], [%1], 16;" :: "r"(saddr), "l"(g));
}
__device__ __forceinline__ uint32_t sptr(const void* p) {
    return (uint32_t)__cvta_generic_to_shared(p);
}
__device__ __forceinline__ void stg_cs2(float* p, float a, float b) {
    asm volatile("st.global.cs.v2.f32 [%0], {%1,%2};" :: "l"(p), "f"(a), "f"(b));
}

// ---------------------------------------------------------------------------
// One-time converts: weights fp32 -> fp16
// ---------------------------------------------------------------------------
__global__ void __launch_bounds__(256)
wcvt(const float* __restrict__ Wq, const float* __restrict__ Wk,
     const float* __restrict__ Wv, const float* __restrict__ Wo,
     __half* __restrict__ Wh)
{
    int idx = (blockIdx.x * 256 + threadIdx.x) * 4;
    const float* s = (idx < 262144) ? Wq
                   : (idx < 524288) ? Wk
                   : (idx < 786432) ? Wv : Wo;
    float4 v = *(const float4*)(s + (idx & 262143));
    __half2 h0 = __floats2half2_rn(v.x, v.y);
    __half2 h1 = __floats2half2_rn(v.z, v.w);
    *(uint2*)(Wh + idx) = make_uint2(*(unsigned*)&h0, *(unsigned*)&h1);
}

// inputs fp32 -> fp16 + mask bit-pack (both pure streams, fused)
__global__ void __launch_bounds__(256)
xcvt(const float* __restrict__ q, const float* __restrict__ k,
     const float* __restrict__ v, __half* __restrict__ dst,
     const int* __restrict__ mask, uint32_t* __restrict__ pm)
{
    // mask pack: first 1024 blocks each pack 256 pm words (1/thread)
    if (blockIdx.x < 1024) {
        int widx = blockIdx.x * 256 + threadIdx.x;
        const int4* mp = (const int4*)(mask + (size_t)widx * 32);
        uint32_t u = 0;
        #pragma unroll
        for (int j = 0; j < 8; j++) {
            int4 m = __ldg(mp + j);
            u |= (m.x != 0 ? 1u : 0u) << (j * 4);
            u |= (m.y != 0 ? 1u : 0u) << (j * 4 + 1);
            u |= (m.z != 0 ? 1u : 0u) << (j * 4 + 2);
            u |= (m.w != 0 ? 1u : 0u) << (j * 4 + 3);
        }
        pm[widx] = u;
    }

    int idx = (blockIdx.x * 256 + threadIdx.x) * 4;
    const float* s = (idx < 2097152) ? q : (idx < 4194304) ? k : v;
    float4 w = *(const float4*)(s + (idx & 2097151));
    __half2 h0 = __floats2half2_rn(w.x, w.y);
    __half2 h1 = __floats2half2_rn(w.z, w.w);
    *(uint2*)(dst + idx) = make_uint2(*(unsigned*)&h0, *(unsigned*)&h1);
}

// ---------------------------------------------------------------------------
// Unified projection (fp16 X, fp16 W): Y = (X @ W^T + b) * scale
// -> fp16 (Yh) or fp32 (Yf). 128m x 64n, 32-k x3 stages, 3 CTAs/SM.
// ---------------------------------------------------------------------------
struct ProjArgs { const __half* X; const __half* W; const float* b;
                  __half* Yh; float* Yf; float scale; };

#define PJ_STAGE 15360
#define PJ_X(s) ((s) * PJ_STAGE)
#define PJ_W(s) ((s) * PJ_STAGE + 10240)
#define PJ_SMEM (3 * PJ_STAGE)

__global__ void __launch_bounds__(256, 3)
proj_h(ProjArgs a0, ProjArgs a1, ProjArgs a2)
{
    const ProjArgs& A_ = (blockIdx.z == 0) ? a0 : (blockIdx.z == 1) ? a1 : a2;
    const __half* __restrict__ Xg = A_.X;
    const __half* __restrict__ Wg = A_.W;
    const float* __restrict__ bias = A_.b;

    extern __shared__ char psm[];
    const uint32_t sb = sptr(psm);

    const int tid = threadIdx.x;
    const int lane = tid & 31, wid = tid >> 5;
    const int g = lane >> 2, tg = lane & 3;
    const int wm = wid & 3, wn = wid >> 2;
    const int m0 = blockIdx.y * 128, n0 = blockIdx.x * 64;

    auto stage = [&](int k0, int s) {
        #pragma unroll
        for (int j = 0; j < 2; j++) {
            int lin = tid + j * 256;
            int r = lin >> 2, c16 = lin & 3;
            cp16(sb + PJ_X(s) + (uint32_t)r * 80u + (uint32_t)c16 * 16u,
                 Xg + (size_t)(m0 + r) * 512 + k0 + c16 * 8);
        }
        {
            int r = tid >> 2, c16 = tid & 3;
            cp16(sb + PJ_W(s) + (uint32_t)r * 80u + (uint32_t)c16 * 16u,
                 Wg + (size_t)(n0 + r) * 512 + k0 + c16 * 8);
        }
        asm volatile("cp.async.commit_group;");
    };

    float acc[2][4][4] = {};

    stage(0, 0);
    stage(32, 1);
    for (int t = 0; t < 16; t++) {
        if (t < 15) asm volatile("cp.async.wait_group 1;");
        else        asm volatile("cp.async.wait_group 0;");
        __syncthreads();
        if (t + 2 < 16) stage((t + 2) * 32, (t + 2) % 3);

        const __half* Xs = (const __half*)(psm + PJ_X(t % 3));
        const __half* Ws = (const __half*)(psm + PJ_W(t % 3));

        #pragma unroll
        for (int ks = 0; ks < 2; ks++) {
            unsigned af[2][4], bf[4][2];
            #pragma unroll
            for (int mi = 0; mi < 2; mi++) {
                const __half* x0 = &Xs[(wm * 32 + mi * 16 + g) * 40 + ks * 16 + 2 * tg];
                const __half* x1 = x0 + 8 * 40;
                af[mi][0] = *(const uint32_t*)x0;
                af[mi][1] = *(const uint32_t*)x1;
                af[mi][2] = *(const uint32_t*)(x0 + 8);
                af[mi][3] = *(const uint32_t*)(x1 + 8);
            }
            #pragma unroll
            for (int ni = 0; ni < 4; ni++) {
                const __half* bb = &Ws[(wn * 32 + ni * 8 + g) * 40 + ks * 16 + 2 * tg];
                bf[ni][0] = *(const uint32_t*)bb;
                bf[ni][1] = *(const uint32_t*)(bb + 8);
            }
            #pragma unroll
            for (int mi = 0; mi < 2; mi++)
                #pragma unroll
                for (int ni = 0; ni < 4; ni++)
                    mmah(acc[mi][ni], af[mi], bf[ni]);
        }
    }

    const float scale = A_.scale;
    #pragma unroll
    for (int mi = 0; mi < 2; mi++) {
        int r0 = m0 + wm * 32 + mi * 16 + g;
        #pragma unroll
        for (int ni = 0; ni < 4; ni++) {
            int c0 = n0 + wn * 32 + ni * 8 + 2 * tg;
            float b0v = __ldg(bias + c0), b1v = __ldg(bias + c0 + 1);
            float y00 = acc[mi][ni][0] + b0v, y01 = acc[mi][ni][1] + b1v;
            float y10 = acc[mi][ni][2] + b0v, y11 = acc[mi][ni][3] + b1v;
            if (A_.Yh) {
                *(unsigned*)(A_.Yh + (size_t)r0 * 512 + c0) = f2h2(y00 * scale, y01 * scale);
                *(unsigned*)(A_.Yh + (size_t)(r0 + 8) * 512 + c0) = f2h2(y10 * scale, y11 * scale);
            } else {
                *(float2*)(A_.Yf + (size_t)r0 * 512 + c0) = make_float2(y00, y01);
                *(float2*)(A_.Yf + (size_t)(r0 + 8) * 512 + c0) = make_float2(y10, y11);
            }
        }
    }
}

// ---------------------------------------------------------------------------
// vtrans: Vh [b,s,hid] -> Vt [z][d][s]  (slim, pack moved to xcvt)
// ---------------------------------------------------------------------------
__global__ void __launch_bounds__(256)
vtrans(const __half* __restrict__ Vh, __half* __restrict__ Vt)
{
    __shared__ __half ts[64 * 72];
    const int tid = threadIdx.x;
    const int z = blockIdx.y, bB = z >> 3, h = z & 7;
    const int s0 = blockIdx.x * 64;

    #pragma unroll
    for (int j = 0; j < 8; j++) {
        int lin = tid + j * 256;
        int s = lin >> 5, du = lin & 31;
        *(uint32_t*)(ts + s * 72 + du * 2) =
            *(const uint32_t*)(Vh + (size_t)(bB * S_ + s0 + s) * HID_ + h * 64 + du * 2);
    }
    __syncthreads();
    #pragma unroll
    for (int j = 0; j < 8; j++) {
        int lin = tid + j * 256;
        int d = lin >> 5, su = lin & 31;
        __half2 o = __halves2half2(ts[(2 * su) * 72 + d], ts[(2 * su + 1) * 72 + d]);
        *(__half2*)(Vt + ((size_t)z * 64 + d) * S_ + s0 + su * 2) = o;
    }
}

// ---------------------------------------------------------------------------
// attn_A: scores+exp -> rowsum + PV (register P). ldmatrix fragment feeds.
// Outputs rowinv + Xh (fp16). No attn write.
// ---------------------------------------------------------------------------
#define SMB_Q    0u
#define SMB_K(s) (9216u + (s) * 18432u)
#define SMB_V(s) (64512u + (s) * 17408u)
#define SMB_RS   116736u
#define ATTN_SMEM (117008 + 16)

__global__ void __launch_bounds__(512, 1)
attn_A(const __half* __restrict__ Qh, const __half* __restrict__ Kh,
       const __half* __restrict__ Vtg, const uint32_t* __restrict__ pm,
       float* __restrict__ rowinv, __half* __restrict__ Xo)
{
    extern __shared__ char smg[];
    const uint32_t sb = sptr(smg);

    const int tid = threadIdx.x, lane = tid & 31, w = tid >> 5;
    const int g = lane >> 2, tg = lane & 3;
    const int wm = w & 3, wn = w >> 2;
    const int z = blockIdx.y, strip = blockIdx.x;
    const int bB = z >> 3, h = z & 7;
    const int s0 = strip * 64;

    float* rows = (float*)(smg + SMB_RS);
    if (tid < 64) rows[tid] = 0.f;

    const __half* Qsrc = Qh + (size_t)(bB * S_ + s0) * HID_ + h * 64;
    const __half* Ksrc = Kh + (size_t)(bB * S_) * HID_ + h * 64;
    const __half* Vsrc = Vtg + (size_t)z * 64 * S_;

    const uint32_t so_sc = (uint32_t)(wn * 32 + (lane & 7)) * 144u
                         + ((lane >> 4) & 1) * 32u + ((lane >> 3) & 1) * 16u;
    const uint32_t so_pv = (uint32_t)(lane & 7) * 272u + (uint32_t)wn * 64u
                         + ((lane >> 4) & 1) * 32u + ((lane >> 3) & 1) * 16u;

    auto loadKV = [&](int chunk, int st) {
        const int kb = chunk * 128;
        #pragma unroll
        for (int j = 0; j < 2; j++) {
            int idx = tid + j * 512;
            int r = idx >> 3, c16 = idx & 7;
            cp16(sb + SMB_K(st) + (uint32_t)r * 144u + (uint32_t)c16 * 16u,
                 Ksrc + (size_t)(kb + r) * HID_ + c16 * 8);
        }
        #pragma unroll
        for (int j = 0; j < 2; j++) {
            int idx = tid + j * 512;
            int d = idx >> 4, c16 = idx & 15;
            cp16(sb + SMB_V(st) + (uint32_t)d * 272u + (uint32_t)c16 * 16u,
                 Vsrc + (size_t)d * S_ + kb + c16 * 8);
        }
        asm volatile("cp.async.commit_group;");
    };

    {
        int r = tid >> 3, c16 = tid & 7;
        cp16(sb + SMB_Q + (uint32_t)r * 144u + (uint32_t)c16 * 16u,
             Qsrc + (size_t)r * HID_ + c16 * 8);
    }
    loadKV(0, 0);
    loadKV(1, 1);
    asm volatile("cp.async.wait_group 1;");
    __syncthreads();

    const __half* Qs = (const __half*)(smg + SMB_Q);
    unsigned qa[4][4];
    #pragma unroll
    for (int ks = 0; ks < 4; ks++) {
        const __half* qr0 = Qs + (wm * 16 + g) * 72 + ks * 16 + 2 * tg;
        const __half* qr1 = qr0 + 8 * 72;
        qa[ks][0] = *(const uint32_t*)qr0;
        qa[ks][1] = *(const uint32_t*)qr1;
        qa[ks][2] = *(const uint32_t*)(qr0 + 8);
        qa[ks][3] = *(const uint32_t*)(qr1 + 8);
    }

    float pvacc[8][4] = {};
    float rsA = 0.f, rsB = 0.f;

    const int rA = bB * S_ + s0 + wm * 16 + g;

    for (int it = 0; it < 16; it++) {
        const int st = it % 3;

        const uint32_t wa = __ldg(pm + (uint32_t)rA * 64u + it * 4 + wn);
        const uint32_t wb = __ldg(pm + (uint32_t)(rA + 8) * 64u + it * 4 + wn);

        if (it > 0) {
            if (it < 15) asm volatile("cp.async.wait_group 1;");
            else         asm volatile("cp.async.wait_group 0;");
            __syncthreads();
        }
        if (it + 2 < 16) loadKV(it + 2, (it + 2) % 3);

        float c[4][4] = {};
        {
            const uint32_t kbase = sb + SMB_K(st) + so_sc;
            #pragma unroll
            for (int p = 0; p < 2; p++) {
                #pragma unroll
                for (int nt = 0; nt < 4; nt++) {
                    uint32_t r0, r1, r2, r3;
                    ldsm4(r0, r1, r2, r3, kbase + (uint32_t)nt * 1152u + (uint32_t)p * 64u);
                    unsigned b0[2] = { r0, r1 }, b1[2] = { r2, r3 };
                    mmah(c[nt], qa[2 * p], b0);
                    mmah(c[nt], qa[2 * p + 1], b1);
                }
            }
        }

        float p[4][4];
        #pragma unroll
        for (int nt = 0; nt < 4; nt++) {
            p[nt][0] = __expf(c[nt][0]);
            p[nt][1] = __expf(c[nt][1]);
            p[nt][2] = __expf(c[nt][2]);
            p[nt][3] = __expf(c[nt][3]);
        }
        if ((wa & wb) != 0xFFFFFFFFu) {
            #pragma unroll
            for (int nt = 0; nt < 4; nt++) {
                int sh = nt * 8 + 2 * tg;
                if (!((wa >> sh) & 1u))       p[nt][0] = 0.f;
                if (!((wa >> (sh + 1)) & 1u)) p[nt][1] = 0.f;
                if (!((wb >> sh) & 1u))       p[nt][2] = 0.f;
                if (!((wb >> (sh + 1)) & 1u)) p[nt][3] = 0.f;
            }
        }
        #pragma unroll
        for (int nt = 0; nt < 4; nt++) {
            rsA += p[nt][0] + p[nt][1];
            rsB += p[nt][2] + p[nt][3];
        }

        unsigned pa[2][4];
        #pragma unroll
        for (int k2 = 0; k2 < 2; k2++) {
            pa[k2][0] = f2h2(p[2 * k2][0], p[2 * k2][1]);
            pa[k2][1] = f2h2(p[2 * k2][2], p[2 * k2][3]);
            pa[k2][2] = f2h2(p[2 * k2 + 1][0], p[2 * k2 + 1][1]);
            pa[k2][3] = f2h2(p[2 * k2 + 1][2], p[2 * k2 + 1][3]);
        }

        {
            const uint32_t vbase = sb + SMB_V(st) + so_pv;
            #pragma unroll
            for (int nt2 = 0; nt2 < 8; nt2++) {
                uint32_t r0, r1, r2, r3;
                ldsm4(r0, r1, r2, r3, vbase + (uint32_t)nt2 * 2176u);
                unsigned b0[2] = { r0, r1 }, b1[2] = { r2, r3 };
                mmah(pvacc[nt2], pa[0], b0);
                mmah(pvacc[nt2], pa[1], b1);
            }
        }
    }

    rsA += __shfl_xor_sync(0xffffffffu, rsA, 1);
    rsA += __shfl_xor_sync(0xffffffffu, rsA, 2);
    rsB += __shfl_xor_sync(0xffffffffu, rsB, 1);
    rsB += __shfl_xor_sync(0xffffffffu, rsB, 2);
    if (tg == 0) {
        atomicAdd(&rows[wm * 16 + g    ], rsA);
        atomicAdd(&rows[wm * 16 + g + 8], rsB);
    }
    __syncthreads();

    if (tid < 64) {
        float inv = 1.0f / rows[tid];
        rows[tid] = inv;
        rowinv[(size_t)z * S_ + s0 + tid] = inv;
    }

    const uint32_t scrOff[4] = { SMB_V(0), SMB_V(1), SMB_V(2), SMB_K(2) };
    {
        float* sw = (float*)(smg + scrOff[wn]);
        #pragma unroll
        for (int nt2 = 0; nt2 < 8; nt2++) {
            int col = nt2 * 8 + 2 * tg;
            *(float2*)&sw[(wm * 16 + g    ) * 64 + col] =
                make_float2(pvacc[nt2][0], pvacc[nt2][1]);
            *(float2*)&sw[(wm * 16 + g + 8) * 64 + col] =
                make_float2(pvacc[nt2][2], pvacc[nt2][3]);
        }
    }
    __syncthreads();

    {
        int r = tid >> 3, cg = (tid & 7) * 8;
        float4 s0v = make_float4(0, 0, 0, 0), s1v = make_float4(0, 0, 0, 0);
        #pragma unroll
        for (int ww = 0; ww < 4; ww++) {
            const float* sw = (const float*)(smg + scrOff[ww]);
            float4 u0 = *(const float4*)&sw[r * 64 + cg];
            float4 u1 = *(const float4*)&sw[r * 64 + cg + 4];
            s0v.x += u0.x; s0v.y += u0.y; s0v.z += u0.z; s0v.w += u0.w;
            s1v.x += u1.x; s1v.y += u1.y; s1v.z += u1.z; s1v.w += u1.w;
        }
        float inv = rows[r];
        uint4 ov;
        ov.x = f2h2(s0v.x * inv, s0v.y * inv);
        ov.y = f2h2(s0v.z * inv, s0v.w * inv);
        ov.z = f2h2(s1v.x * inv, s1v.y * inv);
        ov.w = f2h2(s1v.z * inv, s1v.w * inv);
        *(uint4*)(Xo + (size_t)(bB * S_ + s0 + r) * HID_ + h * 64 + cg) = ov;
    }
}

// ---------------------------------------------------------------------------
// attn_B: recompute scores (ldmatrix feeds), pm fast path + inv rowsum,
// evict-first attn stores. 64-row q-tile, 512 thr, 2 CTAs/SM.
// ---------------------------------------------------------------------------
#define BB_Q    0u
#define BB_K(s) (9216u + (s) * 18432u)
#define ATTNB_SMEM (9216 + 3 * 18432 + 16)

__global__ void __launch_bounds__(512, 2)
attn_B(const __half* __restrict__ Qh, const __half* __restrict__ Kh,
       const uint32_t* __restrict__ pm, const float* __restrict__ rowinv,
       float* __restrict__ attn)
{
    extern __shared__ char smg[];
    const uint32_t sb = sptr(smg);

    const int tid = threadIdx.x, lane = tid & 31, w = tid >> 5;
    const int g = lane >> 2, tg = lane & 3;
    const int wm = w & 3, wn = w >> 2;
    const int z = blockIdx.y, strip = blockIdx.x;
    const int bB = z >> 3, h = z & 7;
    const int s0 = strip * 64;

    const __half* Qsrc = Qh + (size_t)(bB * S_ + s0) * HID_ + h * 64;
    const __half* Ksrc = Kh + (size_t)(bB * S_) * HID_ + h * 64;

    const uint32_t so_sc = (uint32_t)(wn * 32 + (lane & 7)) * 144u
                         + ((lane >> 4) & 1) * 32u + ((lane >> 3) & 1) * 16u;

    auto loadK = [&](int chunk, int st) {
        const int kb = chunk * 128;
        #pragma unroll
        for (int j = 0; j < 2; j++) {
            int idx = tid + j * 512;
            int r = idx >> 3, c16 = idx & 7;
            cp16(sb + BB_K(st) + (uint32_t)r * 144u + (uint32_t)c16 * 16u,
                 Ksrc + (size_t)(kb + r) * HID_ + c16 * 8);
        }
        asm volatile("cp.async.commit_group;");
    };

    {
        int r = tid >> 3, c16 = tid & 7;
        cp16(sb + BB_Q + (uint32_t)r * 144u + (uint32_t)c16 * 16u,
             Qsrc + (size_t)r * HID_ + c16 * 8);
    }
    loadK(0, 0);
    loadK(1, 1);
    asm volatile("cp.async.wait_group 1;");
    __syncthreads();

    const __half* Qs = (const __half*)(smg + BB_Q);
    unsigned qa[4][4];
    #pragma unroll
    for (int ks = 0; ks < 4; ks++) {
        const __half* qr0 = Qs + (wm * 16 + g) * 72 + ks * 16 + 2 * tg;
        const __half* qr1 = qr0 + 8 * 72;
        qa[ks][0] = *(const uint32_t*)qr0;
        qa[ks][1] = *(const uint32_t*)qr1;
        qa[ks][2] = *(const uint32_t*)(qr0 + 8);
        qa[ks][3] = *(const uint32_t*)(qr1 + 8);
    }

    const int rowA = s0 + wm * 16 + g;
    const int rA = bB * S_ + rowA;
    const float invA = __ldg(rowinv + (size_t)z * S_ + rowA);
    const float invB = __ldg(rowinv + (size_t)z * S_ + rowA + 8);
    const size_t arowA = ((size_t)z * S_ + rowA) * S_;
    const size_t arowB = arowA + 8 * S_;

    for (int it = 0; it < 16; it++) {
        const int kb = it * 128;
        const int st = it % 3;

        const uint32_t wa = __ldg(pm + (uint32_t)rA * 64u + it * 4 + wn);
        const uint32_t wb = __ldg(pm + (uint32_t)(rA + 8) * 64u + it * 4 + wn);

        if (it > 0) {
            if (it < 15) asm volatile("cp.async.wait_group 1;");
            else         asm volatile("cp.async.wait_group 0;");
            __syncthreads();
        }
        if (it + 2 < 16) loadK(it + 2, (it + 2) % 3);

        float c[4][4] = {};
        {
            const uint32_t kbase = sb + BB_K(st) + so_sc;
            #pragma unroll
            for (int p = 0; p < 2; p++) {
                #pragma unroll
                for (int nt = 0; nt < 4; nt++) {
                    uint32_t r0, r1, r2, r3;
                    ldsm4(r0, r1, r2, r3, kbase + (uint32_t)nt * 1152u + (uint32_t)p * 64u);
                    unsigned b0[2] = { r0, r1 }, b1[2] = { r2, r3 };
                    mmah(c[nt], qa[2 * p], b0);
                    mmah(c[nt], qa[2 * p + 1], b1);
                }
            }
        }

        float p[4][4];
        #pragma unroll
        for (int nt = 0; nt < 4; nt++) {
            p[nt][0] = __expf(c[nt][0]) * invA;
            p[nt][1] = __expf(c[nt][1]) * invA;
            p[nt][2] = __expf(c[nt][2]) * invB;
            p[nt][3] = __expf(c[nt][3]) * invB;
        }
        if ((wa & wb) != 0xFFFFFFFFu) {
            #pragma unroll
            for (int nt = 0; nt < 4; nt++) {
                int sh = nt * 8 + 2 * tg;
                if (!((wa >> sh) & 1u))       p[nt][0] = 0.f;
                if (!((wa >> (sh + 1)) & 1u)) p[nt][1] = 0.f;
                if (!((wb >> sh) & 1u))       p[nt][2] = 0.f;
                if (!((wb >> (sh + 1)) & 1u)) p[nt][3] = 0.f;
            }
        }
        #pragma unroll
        for (int nt = 0; nt < 4; nt++) {
            int cg = kb + wn * 32 + nt * 8 + 2 * tg;
            stg_cs2(attn + arowA + cg, p[nt][0], p[nt][1]);
            stg_cs2(attn + arowB + cg, p[nt][2], p[nt][3]);
        }
    }
}

// ---------------------------------------------------------------------------
// Launch
// ---------------------------------------------------------------------------
extern "C" void kernel_launch(void* const* d_in, const int* in_sizes, int n_in,
                              void* d_out, int out_size)
{
    const float* q    = (const float*)d_in[0];
    const float* k    = (const float*)d_in[1];
    const float* v    = (const float*)d_in[2];
    const int*   mask = (const int*)  d_in[3];
    const float* Wq   = (const float*)d_in[4];
    const float* bq   = (const float*)d_in[5];
    const float* Wk   = (const float*)d_in[6];
    const float* bk   = (const float*)d_in[7];
    const float* Wv   = (const float*)d_in[8];
    const float* bv   = (const float*)d_in[9];
    const float* Wo   = (const float*)d_in[10];
    const float* bo   = (const float*)d_in[11];

    float* out = (float*)d_out;

    __half *Qhp, *Khp, *Vhp, *Vtp, *Xhp, *Whp, *Xin;
    float *rinv, *scr;
    uint32_t* pmp;
    cudaGetSymbolAddress((void**)&Qhp, g_Qh);
    cudaGetSymbolAddress((void**)&Khp, g_Kh);
    cudaGetSymbolAddress((void**)&Vhp, g_Vh);
    cudaGetSymbolAddress((void**)&Vtp, g_Vt);
    cudaGetSymbolAddress((void**)&Xhp, g_Xh);
    cudaGetSymbolAddress((void**)&Whp, g_Wh);
    cudaGetSymbolAddress((void**)&Xin, g_inx);
    cudaGetSymbolAddress((void**)&rinv, g_rowinv);
    cudaGetSymbolAddress((void**)&pmp, g_pm);
    cudaGetSymbolAddress((void**)&scr, g_attn_scratch);

    const size_t out_elems  = (size_t)M_ * HID_;
    const size_t attn_elems = (size_t)BH_ * S_ * S_;
    float* attn = ((size_t)out_size >= out_elems + attn_elems) ? out + out_elems : scr;

    cudaFuncSetAttribute(attn_A, cudaFuncAttributeMaxDynamicSharedMemorySize, ATTN_SMEM);
    cudaFuncSetAttribute(attn_B, cudaFuncAttributeMaxDynamicSharedMemorySize, ATTNB_SMEM);
    cudaFuncSetAttribute(proj_h, cudaFuncAttributeMaxDynamicSharedMemorySize, PJ_SMEM);

    wcvt<<<1024, 256>>>(Wq, Wk, Wv, Wo, Whp);
    xcvt<<<6144, 256>>>(q, k, v, Xin, mask, pmp);

    ProjArgs pq{Xin,               Whp,          bq, Qhp, nullptr, 0.125f};
    ProjArgs pk{Xin + 2097152,     Whp + 262144, bk, Khp, nullptr, 1.0f};
    ProjArgs pv{Xin + 4194304,     Whp + 524288, bv, Vhp, nullptr, 1.0f};
    proj_h<<<dim3(8, 32, 3), 256, PJ_SMEM>>>(pq, pk, pv);

    vtrans<<<dim3(32, 16), 256>>>(Vhp, Vtp);

    attn_A<<<dim3(32, 16), 512, ATTN_SMEM>>>(Qhp, Khp, Vtp, pmp, rinv, Xhp);

    // Fork: out-projection (tensor-bound) overlaps attn_B (memory-bound);
    // both depend only on attn_A outputs. Event-rooted fork/join so the
    // capture graph carries correct dependencies.
    cudaStream_t s2;
    cudaStreamCreate(&s2);
    cudaEvent_t e1, e2;
    cudaEventCreateWithFlags(&e1, cudaEventDisableTiming);
    cudaEventCreateWithFlags(&e2, cudaEventDisableTiming);

    cudaEventRecord(e1, 0);
    cudaStreamWaitEvent(s2, e1, 0);

    ProjArgs po{Xhp, Whp + 786432, bo, nullptr, out, 1.0f};
    proj_h<<<dim3(8, 32, 1), 256, PJ_SMEM, s2>>>(po, po, po);
    cudaEventRecord(e2, s2);

    attn_B<<<dim3(32, 16), 512, ATTNB_SMEM>>>(Qhp, Khp, pmp, rinv, attn);

    cudaStreamWaitEvent(0, e2, 0);
}